// round 13
// baseline (speedup 1.0000x reference)
#include <cuda_runtime.h>
#include <cuda_fp16.h>
#include <cstdint>
#include <math.h>

#define Bb   2
#define Tt   2048
#define Dd   2048
#define Hh   32
#define HD   64
#define Mrows (Bb*Tt)          // 4096

// ---------------- scratch (__device__ globals) ------------------------------
__device__ uint4 g_xt [(size_t)1024*1024];     // A tiles (plain fp16): x, later y
__device__ uint4 g_wqt[(size_t)512*1024];      // W tiles (plain fp16)
__device__ uint4 g_wkt[(size_t)512*1024];
__device__ uint4 g_wvt[(size_t)512*1024];
__device__ uint4 g_wot[(size_t)512*1024];

// attention planes (plain fp16): Q,K [bh][t][d] ; V [bh][d][t]
__device__ __align__(16) __half g_qh[(size_t)64*2048*64];
__device__ __align__(16) __half g_kh[(size_t)64*2048*64];
__device__ __align__(16) __half g_vh[(size_t)64*2048*64];

// ---------------- PTX helpers ----------------------------------------------
__device__ __forceinline__ uint32_t smem_u32(const void* p) {
    return (uint32_t)__cvta_generic_to_shared(p);
}
__device__ __forceinline__ void mbar_init(uint32_t a, uint32_t cnt) {
    asm volatile("mbarrier.init.shared.b64 [%0], %1;" :: "r"(a), "r"(cnt) : "memory");
}
__device__ __forceinline__ void mbar_expect(uint32_t a, uint32_t tx) {
    asm volatile("mbarrier.arrive.expect_tx.shared.b64 _, [%0], %1;" :: "r"(a), "r"(tx) : "memory");
}
__device__ __forceinline__ void mbar_wait(uint32_t a, int parity) {
    asm volatile(
        "{\n\t.reg .pred P;\n\t"
        "WL_%=:\n\t"
        "mbarrier.try_wait.parity.acquire.cta.shared::cta.b64 P, [%0], %1, 0x989680;\n\t"
        "@P bra WD_%=;\n\t"
        "bra WL_%=;\n\t"
        "WD_%=:\n\t}"
        :: "r"(a), "r"(parity) : "memory");
}
__device__ __forceinline__ void bulk_g2s(uint32_t dst, const void* src, uint32_t bytes, uint32_t mbar) {
    asm volatile(
        "cp.async.bulk.shared::cluster.global.mbarrier::complete_tx::bytes [%0], [%1], %2, [%3];"
        :: "r"(dst), "l"(src), "r"(bytes), "r"(mbar) : "memory");
}
__device__ __forceinline__ void cpa16(uint32_t dst, const void* src) {
    asm volatile("cp.async.cg.shared.global [%0], [%1], 16;" :: "r"(dst), "l"(src) : "memory");
}
__device__ __forceinline__ void cpa_commit() {
    asm volatile("cp.async.commit_group;" ::: "memory");
}
__device__ __forceinline__ void ldmx4(uint32_t* r, uint32_t addr) {
    asm volatile("ldmatrix.sync.aligned.m8n8.x4.shared.b16 {%0,%1,%2,%3}, [%4];"
                 : "=r"(r[0]), "=r"(r[1]), "=r"(r[2]), "=r"(r[3]) : "r"(addr));
}
__device__ __forceinline__ void mma16816(float* d, const uint32_t* a, const uint32_t* b) {
    asm volatile(
        "mma.sync.aligned.m16n8k16.row.col.f32.f16.f16.f32 "
        "{%0,%1,%2,%3}, {%4,%5,%6,%7}, {%8,%9}, {%0,%1,%2,%3};"
        : "+f"(d[0]), "+f"(d[1]), "+f"(d[2]), "+f"(d[3])
        : "r"(a[0]), "r"(a[1]), "r"(a[2]), "r"(a[3]), "r"(b[0]), "r"(b[1]));
}
__device__ __forceinline__ uint32_t pack2h(float v0, float v1) {
    __half2 p = __float22half2_rn(make_float2(v0, v1));
    return *(uint32_t*)&p;
}
__device__ __forceinline__ float ex2f(float x) {
    float y;
    asm("ex2.approx.ftz.f32 %0, %1;" : "=f"(y) : "f"(x));
    return y;
}

// ---------------------------------------------------------------------------
// Convert fp32 -> plain fp16, tiled 16KB chunks, SW128. One launch covers the
// 4 weights (grid.y 0..3) and x (grid.y 4..5, 2048 rows per half).
// ---------------------------------------------------------------------------
__global__ __launch_bounds__(256) void conv_all(
    const float* __restrict__ w0, const float* __restrict__ w1,
    const float* __restrict__ w2, const float* __restrict__ w3,
    const float* __restrict__ xs,
    uint4* __restrict__ d0, uint4* __restrict__ d1,
    uint4* __restrict__ d2, uint4* __restrict__ d3,
    uint4* __restrict__ dx)
{
    const int which = blockIdx.y;
    const float* src;
    uint4* dst;
    int row = blockIdx.x;
    if (which < 4) {
        src = which == 0 ? w0 : which == 1 ? w1 : which == 2 ? w2 : w3;
        dst = which == 0 ? d0 : which == 1 ? d1 : which == 2 ? d2 : d3;
    } else {
        src = xs + (size_t)(which - 4) * 2048 * Dd;
        dst = dx + (size_t)(which - 4) * 512 * 1024;
    }

    const int c8  = threadIdx.x;
    const int nt  = row >> 7, r = row & 127;
    const int kc  = c8 >> 3;
    const int c16 = c8 & 7;

    const float4* s = (const float4*)(src + (size_t)row * Dd + c8 * 8);
    float4 f0 = s[0], f1 = s[1];
    float f[8] = {f0.x, f0.y, f0.z, f0.w, f1.x, f1.y, f1.z, f1.w};

    union { __half h[8]; uint4 v; } hv;
#pragma unroll
    for (int i = 0; i < 8; i++) hv.h[i] = __float2half(f[i]);

    uint32_t off = (uint32_t)(r * 128 + c16 * 16);
    uint32_t sw  = off ^ ((off >> 3) & 0x70);
    size_t tb = ((size_t)(nt * 32 + kc)) * 1024;
    dst[tb + sw / 16] = hv.v;
}

// ---------------------------------------------------------------------------
// HMMA GEMM, plain fp16, CTA tile 256x128, warp tile 64x64 (4x2 warps), occ 1.
// 4-stage pipeline, 48KB stages (A = two 16KB row-chunks + B 16KB).
// fused=1: blockIdx.z -> {Q(mode1: RoPE+pre-scale), K(mode3: RoPE), V(mode2)}
// fused=0: fp32 C (wo). Epilogues smem-staged for coalesced writes.
// ---------------------------------------------------------------------------
#define HG_STAGE 49152
#define HG_NSTG  4
#define HG_SMEM  (2048 + HG_NSTG * HG_STAGE)   // ~194KB

__global__ __launch_bounds__(256, 1) void hgemm(
    const uint4* __restrict__ At,
    const uint4* __restrict__ W0, const uint4* __restrict__ W1,
    const uint4* __restrict__ W2,
    float* __restrict__ C,
    __half* __restrict__ qH, __half* __restrict__ kH, __half* __restrict__ vH,
    const float* __restrict__ fcos, const float* __restrict__ fsin,
    int fused)
{
    extern __shared__ char smraw[];
    const uint32_t base = (smem_u32(smraw) + 1023u) & ~1023u;
    const int tid = threadIdx.x, warp = tid >> 5, lane = tid & 31;
    const int bn = blockIdx.x, bm = blockIdx.y;

    const uint4* Wt; int mode;
    if (fused) {
        int z = blockIdx.z;
        Wt = (z == 0) ? W0 : (z == 1) ? W1 : W2;
        mode = (z == 0) ? 1 : (z == 1) ? 3 : 2;
    } else { Wt = W0; mode = 0; }

    const int wm4 = (warp >> 1) * 64;         // 0,64,128,192 (M offset)
    const int wn2 = (warp & 1) * 64;          // 0,64 (N offset)
    const int rA0l = (wm4 & 127) + ((lane >> 3) & 1) * 8 + (lane & 7);
    const uint32_t abase = (uint32_t)((wm4 >> 7) * 16384);
    const int qhA = lane >> 4;
    const int rB0 = wn2 + (lane >> 4) * 8 + (lane & 7);
    const int qhB = (lane >> 3) & 1;

    float acc[4][8][4];
#pragma unroll
    for (int mi = 0; mi < 4; mi++)
#pragma unroll
        for (int nb = 0; nb < 8; nb++)
#pragma unroll
            for (int e = 0; e < 4; e++) acc[mi][nb][e] = 0.f;

    if (tid == 0) {
#pragma unroll
        for (int s = 0; s < HG_NSTG; s++) mbar_init(base + s * 8, 1);
    }
    __syncthreads();

    const uint32_t tiles = base + 1024;
    const int mt0 = bm * 2;
    if (tid == 0) {
#pragma unroll
        for (int s = 0; s < 3; s++) {
            mbar_expect(base + s * 8, HG_STAGE);
            uint32_t st = tiles + s * HG_STAGE;
            bulk_g2s(st,         At + (size_t)(mt0 * 32 + s) * 1024,       16384, base + s * 8);
            bulk_g2s(st + 16384, At + (size_t)((mt0 + 1) * 32 + s) * 1024, 16384, base + s * 8);
            bulk_g2s(st + 32768, Wt + (size_t)(bn * 32 + s) * 1024,        16384, base + s * 8);
        }
    }

    int ph[HG_NSTG] = {0, 0, 0, 0};
    for (int i = 0; i < 32; i++) {
        const int s = i & 3;
        if (tid == 0 && i + 3 < 32) {
            const int s2 = (i + 3) & 3;
            uint32_t full = base + s2 * 8;
            uint32_t st2  = tiles + s2 * HG_STAGE;
            mbar_expect(full, HG_STAGE);
            bulk_g2s(st2,         At + (size_t)(mt0 * 32 + i + 3) * 1024,       16384, full);
            bulk_g2s(st2 + 16384, At + (size_t)((mt0 + 1) * 32 + i + 3) * 1024, 16384, full);
            bulk_g2s(st2 + 32768, Wt + (size_t)(bn * 32 + i + 3) * 1024,        16384, full);
        }
        mbar_wait(base + s * 8, ph[s]); ph[s] ^= 1;

        const uint32_t stg = tiles + s * HG_STAGE;
        const uint32_t sA = stg + abase, sB = stg + 32768;

#pragma unroll
        for (int ks = 0; ks < 4; ks++) {
            uint32_t af[4][4], bf[8][2];
#pragma unroll
            for (int mi = 0; mi < 4; mi++) {
                int row = rA0l + mi * 16;
                uint32_t off = (uint32_t)(row * 128) + (uint32_t)(((ks * 2 + qhA) ^ (row & 7)) << 4);
                ldmx4(af[mi], sA + off);
            }
#pragma unroll
            for (int nj = 0; nj < 4; nj++) {
                int row = rB0 + nj * 16;
                uint32_t off = (uint32_t)(row * 128) + (uint32_t)(((ks * 2 + qhB) ^ (row & 7)) << 4);
                uint32_t t[4];
                ldmx4(t, sB + off);
                bf[nj*2][0] = t[0]; bf[nj*2][1] = t[1];
                bf[nj*2+1][0] = t[2]; bf[nj*2+1][1] = t[3];
            }
#pragma unroll
            for (int mi = 0; mi < 4; mi++)
#pragma unroll
                for (int nb = 0; nb < 8; nb++)
                    mma16816(acc[mi][nb], af[mi], bf[nb]);
        }
        __syncthreads();
    }

    // ---- epilogues (mainloop's final sync passed; tiles smem is free)
    char* smgen = smraw + (int)(tiles - smem_u32(smraw));
    const int bb = (bm * 256) >> 11;
    const int t0 = (bm * 256) & (Tt - 1);

    if (mode == 2) {
        // V: stage transposed fp16 hs[j 0..127][ml 0..255], then [bh][d][t]
        __half* hs = (__half*)smgen;   // stride 264
#pragma unroll
        for (int mi = 0; mi < 4; mi++)
#pragma unroll
            for (int nb = 0; nb < 8; nb++) {
                int jl = wn2 + (lane & 3) * 2 + nb * 8;
#pragma unroll
                for (int half = 0; half < 2; half++) {
                    int ml = wm4 + (lane >> 2) + mi * 16 + half * 8;
                    hs[jl * 264 + ml]       = __float2half(acc[mi][nb][half * 2 + 0]);
                    hs[(jl + 1) * 264 + ml] = __float2half(acc[mi][nb][half * 2 + 1]);
                }
            }
        __syncthreads();
        for (int L = tid; L < 512; L += 256) {
            int j = L >> 2, part = L & 3;
            int d = bn * 128 + j, hh = d >> 6, dd = d & 63;
            __half* dst = vH + ((size_t)(bb * Hh + hh) * HD + dd) * Tt + t0 + part * 64;
            const uint4* srcv = (const uint4*)(hs + j * 264 + part * 64);
#pragma unroll
            for (int u = 0; u < 8; u++)
                *(uint4*)(dst + u * 8) = srcv[u];
        }
        return;
    }

    if (mode == 0) {
        // fp32 C in two 128-row passes
        float* sbf = (float*)smgen;   // [128][132]
#pragma unroll
        for (int p = 0; p < 2; p++) {
            if ((warp >> 2) == p) {
#pragma unroll
                for (int mi = 0; mi < 4; mi++)
#pragma unroll
                    for (int nb = 0; nb < 8; nb++) {
                        int jl = wn2 + (lane & 3) * 2 + nb * 8;
#pragma unroll
                        for (int half = 0; half < 2; half++) {
                            int ml = (wm4 & 127) + (lane >> 2) + mi * 16 + half * 8;
                            sbf[ml * 132 + jl]     = acc[mi][nb][half * 2 + 0];
                            sbf[ml * 132 + jl + 1] = acc[mi][nb][half * 2 + 1];
                        }
                    }
            }
            __syncthreads();
#pragma unroll
            for (int r = warp; r < 128; r += 8) {
                float4 v = *(const float4*)&sbf[r * 132 + lane * 4];
                *(float4*)(C + (size_t)(bm * 256 + p * 128 + r) * Dd + bn * 128 + lane * 4) = v;
            }
            __syncthreads();
        }
        return;
    }

    // modes 1 (Q, pre-scaled) and 3 (K): RoPE + stage packed u32 [256][66]
    {
        uint32_t* sb = (uint32_t*)smgen;
        const float SCQ = (mode == 1) ? 0.18033688f : 1.0f;  // (1/8)*log2(e)
#pragma unroll
        for (int mi = 0; mi < 4; mi++)
#pragma unroll
            for (int nb = 0; nb < 8; nb++) {
                int jl = wn2 + (lane & 3) * 2 + nb * 8;
                int pi = (jl & 63) >> 1;
#pragma unroll
                for (int half = 0; half < 2; half++) {
                    int ml = wm4 + (lane >> 2) + mi * 16 + half * 8;
                    int t  = (bm * 256 + ml) & (Tt - 1);
                    float cv = fcos[t * (HD / 2) + pi], sv = fsin[t * (HD / 2) + pi];
                    float v0 = acc[mi][nb][half * 2 + 0];
                    float v1 = acc[mi][nb][half * 2 + 1];
                    float r0 = (v0 * cv - v1 * sv) * SCQ;
                    float i0 = (v0 * sv + v1 * cv) * SCQ;
                    sb[ml * 66 + (jl >> 1)] = pack2h(r0, i0);
                }
            }
        __syncthreads();
        int hh0 = bn * 2;
        uint32_t* dstp = (uint32_t*)((mode == 1) ? qH : kH);
        for (int L = warp; L < 512; L += 8) {
            int row = L >> 1;
            int hh  = L & 1;
            uint32_t val = sb[row * 66 + hh * 32 + lane];
            dstp[((size_t)(bb * Hh + hh0 + hh) * Tt + t0 + row) * 32 + lane] = val;
        }
    }
}

// ---------------------------------------------------------------------------
// Tensor-core flash attention, fixed-shift softmax, l-sums via ones-MMA.
// Single-pass S and PV, 3-stage cp.async pipeline, 1 sync/iter.
// smem: Q 16K | 3 stages x (K 8K | V 8K) = 64KB.
// ---------------------------------------------------------------------------
#define AT_SMEM (16384 + 3 * 16384)

__global__ __launch_bounds__(256, 2) void attn(
    const __half* __restrict__ qh,
    const __half* __restrict__ kh, const __half* __restrict__ vh,
    uint4* __restrict__ yt)
{
    extern __shared__ char smraw[];
    const uint32_t smb = smem_u32(smraw);
    const int tid = threadIdx.x, warp = tid >> 5, lane = tid & 31;
    const int qt = (int)gridDim.x - 1 - (int)blockIdx.x;
    const int h  = blockIdx.y, b = blockIdx.z;
    const int bh = b * Hh + h;
    const int ktmax = 2 * qt + 2;

    // ---- group 0: Q into smem (128 rows; 2 threads per row)
    {
        int r = tid >> 1, half = tid & 1;
        const __half* src = qh + ((size_t)bh * Tt + qt * 128 + r) * HD;
        uint32_t dst = smb + r * 128;
#pragma unroll
        for (int cc = 0; cc < 4; cc++) {
            int c = half * 4 + cc;
            cpa16(dst + (uint32_t)(((c ^ (r & 7)) << 4)), src + c * 8);
        }
    }
    cpa_commit();
    // ---- stage loader geometry
    const int srow = tid >> 1, shalf = tid & 1;
#pragma unroll
    for (int s0 = 0; s0 < 2; s0++) {
        uint32_t dst; const __half* src;
        uint32_t sbase = smb + 16384 + (uint32_t)(s0 * 16384);
        if (srow < 64) {
            dst = sbase + srow * 128;
            src = kh + ((size_t)bh * Tt + s0 * 64 + srow) * HD;
        } else {
            int d = srow - 64;
            dst = sbase + 8192 + d * 128;
            src = vh + ((size_t)bh * HD + d) * Tt + s0 * 64;
        }
#pragma unroll
        for (int cc = 0; cc < 4; cc++) {
            int c = shalf * 4 + cc;
            cpa16(dst + (uint32_t)(((c ^ (srow & 7)) << 4)), src + c * 8);
        }
        cpa_commit();
    }

    const int g    = lane >> 2;
    const int tc2  = (lane & 3) * 2;
    const int rA0  = warp * 16 + ((lane >> 3) & 1) * 8 + (lane & 7);
    const int qhA  = lane >> 4;
    const int rB0  = (lane >> 4) * 8 + (lane & 7);
    const int qhB  = (lane >> 3) & 1;
    const int row0g = qt * 128 + warp * 16 + g;

    // ---- hoist Q fragments into registers
    uint32_t qf[4][4];
    asm volatile("cp.async.wait_group 2;" ::: "memory");
    __syncthreads();
#pragma unroll
    for (int kg = 0; kg < 4; kg++) {
        uint32_t offA = (uint32_t)(rA0 * 128) + (uint32_t)(((kg * 2 + qhA) ^ (rA0 & 7)) << 4);
        ldmx4(qf[kg], smb + offA);
    }

    float oa[8][4];
#pragma unroll
    for (int nb = 0; nb < 8; nb++)
#pragma unroll
        for (int e = 0; e < 4; e++) oa[nb][e] = 0.f;
    float lacc[4] = {0.f, 0.f, 0.f, 0.f};           // ones-MMA row-sum acc
    const uint32_t bones[2] = {0x3C003C00u, 0x3C003C00u};  // fp16 1.0 frag

    for (int kt = 0; kt < ktmax; kt++) {
        const uint32_t stage = smb + 16384 + (uint32_t)((kt % 3) * 16384);
        asm volatile("cp.async.wait_group 1;" ::: "memory");
        __syncthreads();

        if (kt + 2 < ktmax) {
            uint32_t sbase = smb + 16384 + (uint32_t)(((kt + 2) % 3) * 16384);
            uint32_t dst; const __half* src;
            if (srow < 64) {
                dst = sbase + srow * 128;
                src = kh + ((size_t)bh * Tt + (kt + 2) * 64 + srow) * HD;
            } else {
                int d = srow - 64;
                dst = sbase + 8192 + d * 128;
                src = vh + ((size_t)bh * HD + d) * Tt + (kt + 2) * 64;
            }
#pragma unroll
            for (int cc = 0; cc < 4; cc++) {
                int c = shalf * 4 + cc;
                cpa16(dst + (uint32_t)(((c ^ (srow & 7)) << 4)), src + c * 8);
            }
        }
        cpa_commit();

        // ---- S = Q K^T (single pass; Q pre-scaled into log2 units)
        float sa[8][4];
#pragma unroll
        for (int nb = 0; nb < 8; nb++)
#pragma unroll
            for (int e = 0; e < 4; e++) sa[nb][e] = 0.f;

#pragma unroll
        for (int kg = 0; kg < 4; kg++) {
#pragma unroll
            for (int nj = 0; nj < 4; nj++) {
                int rB = rB0 + nj * 16;
                uint32_t offB = (uint32_t)(rB * 128) + (uint32_t)(((kg * 2 + qhB) ^ (rB & 7)) << 4);
                uint32_t th[4];
                ldmx4(th, stage + offB);
                mma16816(sa[nj*2],   qf[kg], th);
                mma16816(sa[nj*2+1], qf[kg], th + 2);
            }
        }

        // ---- causal mask + fixed-shift exp2 (single MUFU per element)
        const bool dm = (kt >= 2 * qt);
#pragma unroll
        for (int nb = 0; nb < 8; nb++) {
            if (dm) {
                int colb = kt * 64 + nb * 8 + tc2;
                if (colb     > row0g)     sa[nb][0] = -1e30f;
                if (colb + 1 > row0g)     sa[nb][1] = -1e30f;
                if (colb     > row0g + 8) sa[nb][2] = -1e30f;
                if (colb + 1 > row0g + 8) sa[nb][3] = -1e30f;
            }
            sa[nb][0] = ex2f(sa[nb][0]);
            sa[nb][1] = ex2f(sa[nb][1]);
            sa[nb][2] = ex2f(sa[nb][2]);
            sa[nb][3] = ex2f(sa[nb][3]);
        }

        // ---- O += P V; l += P @ ones (single pass, P plain fp16)
#pragma unroll
        for (int kg = 0; kg < 4; kg++) {
            float* c0 = sa[2 * kg];
            float* c1 = sa[2 * kg + 1];
            uint32_t ap[4];
            ap[0] = pack2h(c0[0], c0[1]);
            ap[1] = pack2h(c0[2], c0[3]);
            ap[2] = pack2h(c1[0], c1[1]);
            ap[3] = pack2h(c1[2], c1[3]);
            mma16816(lacc, ap, bones);
#pragma unroll
            for (int nj = 0; nj < 4; nj++) {
                int rB = rB0 + nj * 16;
                uint32_t offB = (uint32_t)(rB * 128) + (uint32_t)(((kg * 2 + qhB) ^ (rB & 7)) << 4);
                uint32_t bv[4];
                ldmx4(bv, stage + 8192 + offB);
                mma16816(oa[nj*2],   ap, bv);
                mma16816(oa[nj*2+1], ap, bv + 2);
            }
        }
    }

    // lacc columns are identical; [0] = rowsum(row g), [2] = rowsum(row g+8)
    float inv0 = 1.f / lacc[0], inv1 = 1.f / lacc[2];
    uint32_t tb = (uint32_t)(((b * 16 + qt) * 32 + h) * 16384);
    uint32_t* y32 = (uint32_t*)yt;
    const int r0 = warp * 16 + g, r1 = r0 + 8;
#pragma unroll
    for (int nb = 0; nb < 8; nb++) {
        int d0 = nb * 8 + tc2;
        uint32_t off0 = (uint32_t)(r0 * 128 + d0 * 2);
        uint32_t sw0  = off0 ^ ((off0 >> 3) & 0x70);
        y32[(tb + sw0) >> 2] = pack2h(oa[nb][0] * inv0, oa[nb][1] * inv0);
        uint32_t off1 = (uint32_t)(r1 * 128 + d0 * 2);
        uint32_t sw1  = off1 ^ ((off1 >> 3) & 0x70);
        y32[(tb + sw1) >> 2] = pack2h(oa[nb][2] * inv1, oa[nb][3] * inv1);
    }
}

// ---------------------------------------------------------------------------
extern "C" void kernel_launch(void* const* d_in, const int* in_sizes, int n_in,
                              void* d_out, int out_size)
{
    const float* x    = (const float*)d_in[0];
    const float* fcos = (const float*)d_in[1];
    const float* fsin = (const float*)d_in[2];
    const float* wq   = (const float*)d_in[3];
    const float* wk   = (const float*)d_in[4];
    const float* wv   = (const float*)d_in[5];
    const float* wo   = (const float*)d_in[6];
    float* out = (float*)d_out;

    uint4 *xt, *wqt, *wkt, *wvt, *wot;
    __half *qh, *kh, *vh;
    cudaGetSymbolAddress((void**)&xt, g_xt);
    cudaGetSymbolAddress((void**)&wqt, g_wqt);
    cudaGetSymbolAddress((void**)&wkt, g_wkt);
    cudaGetSymbolAddress((void**)&wvt, g_wvt);
    cudaGetSymbolAddress((void**)&wot, g_wot);
    cudaGetSymbolAddress((void**)&qh, g_qh);
    cudaGetSymbolAddress((void**)&kh, g_kh);
    cudaGetSymbolAddress((void**)&vh, g_vh);

    cudaFuncSetAttribute(hgemm, cudaFuncAttributeMaxDynamicSharedMemorySize, HG_SMEM);
    cudaFuncSetAttribute(attn,  cudaFuncAttributeMaxDynamicSharedMemorySize, AT_SMEM);

    dim3 cgrid(2048, 6);   // 4 weights + x (2 halves)
    conv_all<<<cgrid, 256>>>(wq, wk, wv, wo, x, wqt, wkt, wvt, wot, xt);

    dim3 ggrid3(Dd / 128, Mrows / 256, 3);   // fused QKV (16,16,3)
    hgemm<<<ggrid3, 256, HG_SMEM>>>(xt, wqt, wkt, wvt, nullptr,
                                    qh, kh, vh, fcos, fsin, 1);

    dim3 agrid(Tt / 128, Hh, Bb);            // (16, 32, 2)
    attn<<<agrid, 256, AT_SMEM>>>(qh, kh, vh, xt);

    dim3 ggrid(Dd / 128, Mrows / 256, 1);    // wo (16,16)
    hgemm<<<ggrid, 256, HG_SMEM>>>(xt, wot, nullptr, nullptr, out,
                                   nullptr, nullptr, nullptr, fcos, fsin, 0);
}

// round 14
// speedup vs baseline: 1.0414x; 1.0414x over previous
#include <cuda_runtime.h>
#include <cuda_fp16.h>
#include <cstdint>
#include <math.h>

#define Bb   2
#define Tt   2048
#define Dd   2048
#define Hh   32
#define HD   64
#define Mrows (Bb*Tt)          // 4096

// ---------------- scratch (__device__ globals) ------------------------------
__device__ uint4 g_xt [(size_t)1024*1024];     // A tiles (plain fp16): x, later y
__device__ uint4 g_wqt[(size_t)512*1024];      // W tiles (plain fp16)
__device__ uint4 g_wkt[(size_t)512*1024];
__device__ uint4 g_wvt[(size_t)512*1024];
__device__ uint4 g_wot[(size_t)512*1024];

// attention planes (plain fp16): Q,K [bh][t][d] ; V [bh][d][t]
__device__ __align__(16) __half g_qh[(size_t)64*2048*64];
__device__ __align__(16) __half g_kh[(size_t)64*2048*64];
__device__ __align__(16) __half g_vh[(size_t)64*2048*64];

// ---------------- PTX helpers ----------------------------------------------
__device__ __forceinline__ uint32_t smem_u32(const void* p) {
    return (uint32_t)__cvta_generic_to_shared(p);
}
__device__ __forceinline__ void mbar_init(uint32_t a, uint32_t cnt) {
    asm volatile("mbarrier.init.shared.b64 [%0], %1;" :: "r"(a), "r"(cnt) : "memory");
}
__device__ __forceinline__ void mbar_expect(uint32_t a, uint32_t tx) {
    asm volatile("mbarrier.arrive.expect_tx.shared.b64 _, [%0], %1;" :: "r"(a), "r"(tx) : "memory");
}
__device__ __forceinline__ void mbar_wait(uint32_t a, int parity) {
    asm volatile(
        "{\n\t.reg .pred P;\n\t"
        "WL_%=:\n\t"
        "mbarrier.try_wait.parity.acquire.cta.shared::cta.b64 P, [%0], %1, 0x989680;\n\t"
        "@P bra WD_%=;\n\t"
        "bra WL_%=;\n\t"
        "WD_%=:\n\t}"
        :: "r"(a), "r"(parity) : "memory");
}
__device__ __forceinline__ void bulk_g2s(uint32_t dst, const void* src, uint32_t bytes, uint32_t mbar) {
    asm volatile(
        "cp.async.bulk.shared::cluster.global.mbarrier::complete_tx::bytes [%0], [%1], %2, [%3];"
        :: "r"(dst), "l"(src), "r"(bytes), "r"(mbar) : "memory");
}
__device__ __forceinline__ void cpa16(uint32_t dst, const void* src) {
    asm volatile("cp.async.cg.shared.global [%0], [%1], 16;" :: "r"(dst), "l"(src) : "memory");
}
__device__ __forceinline__ void cpa_commit() {
    asm volatile("cp.async.commit_group;" ::: "memory");
}
__device__ __forceinline__ void ldmx4(uint32_t* r, uint32_t addr) {
    asm volatile("ldmatrix.sync.aligned.m8n8.x4.shared.b16 {%0,%1,%2,%3}, [%4];"
                 : "=r"(r[0]), "=r"(r[1]), "=r"(r[2]), "=r"(r[3]) : "r"(addr));
}
__device__ __forceinline__ void mma16816(float* d, const uint32_t* a, const uint32_t* b) {
    asm volatile(
        "mma.sync.aligned.m16n8k16.row.col.f32.f16.f16.f32 "
        "{%0,%1,%2,%3}, {%4,%5,%6,%7}, {%8,%9}, {%0,%1,%2,%3};"
        : "+f"(d[0]), "+f"(d[1]), "+f"(d[2]), "+f"(d[3])
        : "r"(a[0]), "r"(a[1]), "r"(a[2]), "r"(a[3]), "r"(b[0]), "r"(b[1]));
}
__device__ __forceinline__ uint32_t pack2h(float v0, float v1) {
    __half2 p = __float22half2_rn(make_float2(v0, v1));
    return *(uint32_t*)&p;
}
__device__ __forceinline__ float ex2f(float x) {
    float y;
    asm("ex2.approx.ftz.f32 %0, %1;" : "=f"(y) : "f"(x));
    return y;
}

// ---------------------------------------------------------------------------
// Convert fp32 -> plain fp16, tiled 16KB chunks, SW128. One launch covers the
// 4 weights (grid.y 0..3) and x (grid.y 4..5, 2048 rows per half).
// ---------------------------------------------------------------------------
__global__ __launch_bounds__(256) void conv_all(
    const float* __restrict__ w0, const float* __restrict__ w1,
    const float* __restrict__ w2, const float* __restrict__ w3,
    const float* __restrict__ xs,
    uint4* __restrict__ d0, uint4* __restrict__ d1,
    uint4* __restrict__ d2, uint4* __restrict__ d3,
    uint4* __restrict__ dx)
{
    const int which = blockIdx.y;
    const float* src;
    uint4* dst;
    int row = blockIdx.x;
    if (which < 4) {
        src = which == 0 ? w0 : which == 1 ? w1 : which == 2 ? w2 : w3;
        dst = which == 0 ? d0 : which == 1 ? d1 : which == 2 ? d2 : d3;
    } else {
        src = xs + (size_t)(which - 4) * 2048 * Dd;
        dst = dx + (size_t)(which - 4) * 512 * 1024;
    }

    const int c8  = threadIdx.x;
    const int nt  = row >> 7, r = row & 127;
    const int kc  = c8 >> 3;
    const int c16 = c8 & 7;

    const float4* s = (const float4*)(src + (size_t)row * Dd + c8 * 8);
    float4 f0 = s[0], f1 = s[1];
    float f[8] = {f0.x, f0.y, f0.z, f0.w, f1.x, f1.y, f1.z, f1.w};

    union { __half h[8]; uint4 v; } hv;
#pragma unroll
    for (int i = 0; i < 8; i++) hv.h[i] = __float2half(f[i]);

    uint32_t off = (uint32_t)(r * 128 + c16 * 16);
    uint32_t sw  = off ^ ((off >> 3) & 0x70);
    size_t tb = ((size_t)(nt * 32 + kc)) * 1024;
    dst[tb + sw / 16] = hv.v;
}

// ---------------------------------------------------------------------------
// HMMA GEMM, plain fp16, CTA tile 256x128, warp tile 64x64 (4x2 warps), occ 1.
// 3-stage pipeline (R12 config), 48KB stages (A = two 16KB chunks + B 16KB).
// fused=1: blockIdx.z -> {Q(mode1: RoPE+pre-scale), K(mode3: RoPE), V(mode2)}
// fused=0: fp32 C (wo). Epilogues smem-staged for coalesced writes.
// ---------------------------------------------------------------------------
#define HG_STAGE 49152
#define HG_SMEM  (2048 + 3 * HG_STAGE)   // ~146KB

__global__ __launch_bounds__(256, 1) void hgemm(
    const uint4* __restrict__ At,
    const uint4* __restrict__ W0, const uint4* __restrict__ W1,
    const uint4* __restrict__ W2,
    float* __restrict__ C,
    __half* __restrict__ qH, __half* __restrict__ kH, __half* __restrict__ vH,
    const float* __restrict__ fcos, const float* __restrict__ fsin,
    int fused)
{
    extern __shared__ char smraw[];
    const uint32_t base = (smem_u32(smraw) + 1023u) & ~1023u;
    const int tid = threadIdx.x, warp = tid >> 5, lane = tid & 31;
    const int bn = blockIdx.x, bm = blockIdx.y;

    const uint4* Wt; int mode;
    if (fused) {
        int z = blockIdx.z;
        Wt = (z == 0) ? W0 : (z == 1) ? W1 : W2;
        mode = (z == 0) ? 1 : (z == 1) ? 3 : 2;
    } else { Wt = W0; mode = 0; }

    const int wm4 = (warp >> 1) * 64;         // 0,64,128,192 (M offset)
    const int wn2 = (warp & 1) * 64;          // 0,64 (N offset)
    const int rA0l = (wm4 & 127) + ((lane >> 3) & 1) * 8 + (lane & 7);
    const uint32_t abase = (uint32_t)((wm4 >> 7) * 16384);
    const int qhA = lane >> 4;
    const int rB0 = wn2 + (lane >> 4) * 8 + (lane & 7);
    const int qhB = (lane >> 3) & 1;

    float acc[4][8][4];
#pragma unroll
    for (int mi = 0; mi < 4; mi++)
#pragma unroll
        for (int nb = 0; nb < 8; nb++)
#pragma unroll
            for (int e = 0; e < 4; e++) acc[mi][nb][e] = 0.f;

    if (tid == 0) { mbar_init(base, 1); mbar_init(base + 8, 1); mbar_init(base + 16, 1); }
    __syncthreads();

    const uint32_t tiles = base + 1024;
    const int mt0 = bm * 2;
    if (tid == 0) {
#pragma unroll
        for (int s = 0; s < 2; s++) {
            mbar_expect(base + s * 8, HG_STAGE);
            uint32_t st = tiles + s * HG_STAGE;
            bulk_g2s(st,         At + (size_t)(mt0 * 32 + s) * 1024,       16384, base + s * 8);
            bulk_g2s(st + 16384, At + (size_t)((mt0 + 1) * 32 + s) * 1024, 16384, base + s * 8);
            bulk_g2s(st + 32768, Wt + (size_t)(bn * 32 + s) * 1024,        16384, base + s * 8);
        }
    }

    int ph[3] = {0, 0, 0};
    for (int i = 0; i < 32; i++) {
        const int s = i % 3;
        if (tid == 0 && i + 2 < 32) {
            const int s2 = (i + 2) % 3;
            uint32_t full = base + s2 * 8;
            uint32_t st2  = tiles + s2 * HG_STAGE;
            mbar_expect(full, HG_STAGE);
            bulk_g2s(st2,         At + (size_t)(mt0 * 32 + i + 2) * 1024,       16384, full);
            bulk_g2s(st2 + 16384, At + (size_t)((mt0 + 1) * 32 + i + 2) * 1024, 16384, full);
            bulk_g2s(st2 + 32768, Wt + (size_t)(bn * 32 + i + 2) * 1024,        16384, full);
        }
        mbar_wait(base + s * 8, ph[s]); ph[s] ^= 1;

        const uint32_t stg = tiles + s * HG_STAGE;
        const uint32_t sA = stg + abase, sB = stg + 32768;

#pragma unroll
        for (int ks = 0; ks < 4; ks++) {
            uint32_t af[4][4], bf[8][2];
#pragma unroll
            for (int mi = 0; mi < 4; mi++) {
                int row = rA0l + mi * 16;
                uint32_t off = (uint32_t)(row * 128) + (uint32_t)(((ks * 2 + qhA) ^ (row & 7)) << 4);
                ldmx4(af[mi], sA + off);
            }
#pragma unroll
            for (int nj = 0; nj < 4; nj++) {
                int row = rB0 + nj * 16;
                uint32_t off = (uint32_t)(row * 128) + (uint32_t)(((ks * 2 + qhB) ^ (row & 7)) << 4);
                uint32_t t[4];
                ldmx4(t, sB + off);
                bf[nj*2][0] = t[0]; bf[nj*2][1] = t[1];
                bf[nj*2+1][0] = t[2]; bf[nj*2+1][1] = t[3];
            }
#pragma unroll
            for (int mi = 0; mi < 4; mi++)
#pragma unroll
                for (int nb = 0; nb < 8; nb++)
                    mma16816(acc[mi][nb], af[mi], bf[nb]);
        }
        __syncthreads();
    }

    // ---- epilogues (mainloop's final sync passed; tiles smem is free)
    char* smgen = smraw + (int)(tiles - smem_u32(smraw));
    const int bb = (bm * 256) >> 11;
    const int t0 = (bm * 256) & (Tt - 1);

    if (mode == 2) {
        // V: stage transposed fp16 hs[j 0..127][ml 0..255], then [bh][d][t]
        __half* hs = (__half*)smgen;   // stride 264
#pragma unroll
        for (int mi = 0; mi < 4; mi++)
#pragma unroll
            for (int nb = 0; nb < 8; nb++) {
                int jl = wn2 + (lane & 3) * 2 + nb * 8;
#pragma unroll
                for (int half = 0; half < 2; half++) {
                    int ml = wm4 + (lane >> 2) + mi * 16 + half * 8;
                    hs[jl * 264 + ml]       = __float2half(acc[mi][nb][half * 2 + 0]);
                    hs[(jl + 1) * 264 + ml] = __float2half(acc[mi][nb][half * 2 + 1]);
                }
            }
        __syncthreads();
        for (int L = tid; L < 512; L += 256) {
            int j = L >> 2, part = L & 3;
            int d = bn * 128 + j, hh = d >> 6, dd = d & 63;
            __half* dst = vH + ((size_t)(bb * Hh + hh) * HD + dd) * Tt + t0 + part * 64;
            const uint4* srcv = (const uint4*)(hs + j * 264 + part * 64);
#pragma unroll
            for (int u = 0; u < 8; u++)
                *(uint4*)(dst + u * 8) = srcv[u];
        }
        return;
    }

    if (mode == 0) {
        // fp32 C in two 128-row passes
        float* sbf = (float*)smgen;   // [128][132]
#pragma unroll
        for (int p = 0; p < 2; p++) {
            if ((warp >> 2) == p) {
#pragma unroll
                for (int mi = 0; mi < 4; mi++)
#pragma unroll
                    for (int nb = 0; nb < 8; nb++) {
                        int jl = wn2 + (lane & 3) * 2 + nb * 8;
#pragma unroll
                        for (int half = 0; half < 2; half++) {
                            int ml = (wm4 & 127) + (lane >> 2) + mi * 16 + half * 8;
                            sbf[ml * 132 + jl]     = acc[mi][nb][half * 2 + 0];
                            sbf[ml * 132 + jl + 1] = acc[mi][nb][half * 2 + 1];
                        }
                    }
            }
            __syncthreads();
#pragma unroll
            for (int r = warp; r < 128; r += 8) {
                float4 v = *(const float4*)&sbf[r * 132 + lane * 4];
                *(float4*)(C + (size_t)(bm * 256 + p * 128 + r) * Dd + bn * 128 + lane * 4) = v;
            }
            __syncthreads();
        }
        return;
    }

    // modes 1 (Q, pre-scaled) and 3 (K): RoPE + stage packed u32 [256][66]
    {
        uint32_t* sb = (uint32_t*)smgen;
        const float SCQ = (mode == 1) ? 0.18033688f : 1.0f;  // (1/8)*log2(e)
#pragma unroll
        for (int mi = 0; mi < 4; mi++)
#pragma unroll
            for (int nb = 0; nb < 8; nb++) {
                int jl = wn2 + (lane & 3) * 2 + nb * 8;
                int pi = (jl & 63) >> 1;
#pragma unroll
                for (int half = 0; half < 2; half++) {
                    int ml = wm4 + (lane >> 2) + mi * 16 + half * 8;
                    int t  = (bm * 256 + ml) & (Tt - 1);
                    float cv = fcos[t * (HD / 2) + pi], sv = fsin[t * (HD / 2) + pi];
                    float v0 = acc[mi][nb][half * 2 + 0];
                    float v1 = acc[mi][nb][half * 2 + 1];
                    float r0 = (v0 * cv - v1 * sv) * SCQ;
                    float i0 = (v0 * sv + v1 * cv) * SCQ;
                    sb[ml * 66 + (jl >> 1)] = pack2h(r0, i0);
                }
            }
        __syncthreads();
        int hh0 = bn * 2;
        uint32_t* dstp = (uint32_t*)((mode == 1) ? qH : kH);
        for (int L = warp; L < 512; L += 8) {
            int row = L >> 1;
            int hh  = L & 1;
            uint32_t val = sb[row * 66 + hh * 32 + lane];
            dstp[((size_t)(bb * Hh + hh0 + hh) * Tt + t0 + row) * 32 + lane] = val;
        }
    }
}

// ---------------------------------------------------------------------------
// Tensor-core flash attention, fixed-shift softmax, l-sums via ones-MMA.
// Single-pass S and PV, 3-stage cp.async pipeline, 1 sync/iter.
// smem: Q 16K | 3 stages x (K 8K | V 8K) = 64KB.
// ---------------------------------------------------------------------------
#define AT_SMEM (16384 + 3 * 16384)

__global__ __launch_bounds__(256, 2) void attn(
    const __half* __restrict__ qh,
    const __half* __restrict__ kh, const __half* __restrict__ vh,
    uint4* __restrict__ yt)
{
    extern __shared__ char smraw[];
    const uint32_t smb = smem_u32(smraw);
    const int tid = threadIdx.x, warp = tid >> 5, lane = tid & 31;
    const int qt = (int)gridDim.x - 1 - (int)blockIdx.x;
    const int h  = blockIdx.y, b = blockIdx.z;
    const int bh = b * Hh + h;
    const int ktmax = 2 * qt + 2;

    // ---- group 0: Q into smem (128 rows; 2 threads per row)
    {
        int r = tid >> 1, half = tid & 1;
        const __half* src = qh + ((size_t)bh * Tt + qt * 128 + r) * HD;
        uint32_t dst = smb + r * 128;
#pragma unroll
        for (int cc = 0; cc < 4; cc++) {
            int c = half * 4 + cc;
            cpa16(dst + (uint32_t)(((c ^ (r & 7)) << 4)), src + c * 8);
        }
    }
    cpa_commit();
    // ---- stage loader geometry
    const int srow = tid >> 1, shalf = tid & 1;
#pragma unroll
    for (int s0 = 0; s0 < 2; s0++) {
        uint32_t dst; const __half* src;
        uint32_t sbase = smb + 16384 + (uint32_t)(s0 * 16384);
        if (srow < 64) {
            dst = sbase + srow * 128;
            src = kh + ((size_t)bh * Tt + s0 * 64 + srow) * HD;
        } else {
            int d = srow - 64;
            dst = sbase + 8192 + d * 128;
            src = vh + ((size_t)bh * HD + d) * Tt + s0 * 64;
        }
#pragma unroll
        for (int cc = 0; cc < 4; cc++) {
            int c = shalf * 4 + cc;
            cpa16(dst + (uint32_t)(((c ^ (srow & 7)) << 4)), src + c * 8);
        }
        cpa_commit();
    }

    const int g    = lane >> 2;
    const int tc2  = (lane & 3) * 2;
    const int rA0  = warp * 16 + ((lane >> 3) & 1) * 8 + (lane & 7);
    const int qhA  = lane >> 4;
    const int rB0  = (lane >> 4) * 8 + (lane & 7);
    const int qhB  = (lane >> 3) & 1;
    const int row0g = qt * 128 + warp * 16 + g;

    // ---- hoist Q fragments into registers
    uint32_t qf[4][4];
    asm volatile("cp.async.wait_group 2;" ::: "memory");
    __syncthreads();
#pragma unroll
    for (int kg = 0; kg < 4; kg++) {
        uint32_t offA = (uint32_t)(rA0 * 128) + (uint32_t)(((kg * 2 + qhA) ^ (rA0 & 7)) << 4);
        ldmx4(qf[kg], smb + offA);
    }

    float oa[8][4];
#pragma unroll
    for (int nb = 0; nb < 8; nb++)
#pragma unroll
        for (int e = 0; e < 4; e++) oa[nb][e] = 0.f;
    float lacc[4] = {0.f, 0.f, 0.f, 0.f};           // ones-MMA row-sum acc
    const uint32_t bones[2] = {0x3C003C00u, 0x3C003C00u};  // fp16 1.0 frag

    for (int kt = 0; kt < ktmax; kt++) {
        const uint32_t stage = smb + 16384 + (uint32_t)((kt % 3) * 16384);
        asm volatile("cp.async.wait_group 1;" ::: "memory");
        __syncthreads();

        if (kt + 2 < ktmax) {
            uint32_t sbase = smb + 16384 + (uint32_t)(((kt + 2) % 3) * 16384);
            uint32_t dst; const __half* src;
            if (srow < 64) {
                dst = sbase + srow * 128;
                src = kh + ((size_t)bh * Tt + (kt + 2) * 64 + srow) * HD;
            } else {
                int d = srow - 64;
                dst = sbase + 8192 + d * 128;
                src = vh + ((size_t)bh * HD + d) * Tt + (kt + 2) * 64;
            }
#pragma unroll
            for (int cc = 0; cc < 4; cc++) {
                int c = shalf * 4 + cc;
                cpa16(dst + (uint32_t)(((c ^ (srow & 7)) << 4)), src + c * 8);
            }
        }
        cpa_commit();

        // ---- S = Q K^T (single pass; Q pre-scaled into log2 units)
        float sa[8][4];
#pragma unroll
        for (int nb = 0; nb < 8; nb++)
#pragma unroll
            for (int e = 0; e < 4; e++) sa[nb][e] = 0.f;

#pragma unroll
        for (int kg = 0; kg < 4; kg++) {
#pragma unroll
            for (int nj = 0; nj < 4; nj++) {
                int rB = rB0 + nj * 16;
                uint32_t offB = (uint32_t)(rB * 128) + (uint32_t)(((kg * 2 + qhB) ^ (rB & 7)) << 4);
                uint32_t th[4];
                ldmx4(th, stage + offB);
                mma16816(sa[nj*2],   qf[kg], th);
                mma16816(sa[nj*2+1], qf[kg], th + 2);
            }
        }

        // ---- causal mask + fixed-shift exp2 (single MUFU per element)
        const bool dm = (kt >= 2 * qt);
#pragma unroll
        for (int nb = 0; nb < 8; nb++) {
            if (dm) {
                int colb = kt * 64 + nb * 8 + tc2;
                if (colb     > row0g)     sa[nb][0] = -1e30f;
                if (colb + 1 > row0g)     sa[nb][1] = -1e30f;
                if (colb     > row0g + 8) sa[nb][2] = -1e30f;
                if (colb + 1 > row0g + 8) sa[nb][3] = -1e30f;
            }
            sa[nb][0] = ex2f(sa[nb][0]);
            sa[nb][1] = ex2f(sa[nb][1]);
            sa[nb][2] = ex2f(sa[nb][2]);
            sa[nb][3] = ex2f(sa[nb][3]);
        }

        // ---- O += P V; l += P @ ones (single pass, P plain fp16)
#pragma unroll
        for (int kg = 0; kg < 4; kg++) {
            float* c0 = sa[2 * kg];
            float* c1 = sa[2 * kg + 1];
            uint32_t ap[4];
            ap[0] = pack2h(c0[0], c0[1]);
            ap[1] = pack2h(c0[2], c0[3]);
            ap[2] = pack2h(c1[0], c1[1]);
            ap[3] = pack2h(c1[2], c1[3]);
            mma16816(lacc, ap, bones);
#pragma unroll
            for (int nj = 0; nj < 4; nj++) {
                int rB = rB0 + nj * 16;
                uint32_t offB = (uint32_t)(rB * 128) + (uint32_t)(((kg * 2 + qhB) ^ (rB & 7)) << 4);
                uint32_t bv[4];
                ldmx4(bv, stage + 8192 + offB);
                mma16816(oa[nj*2],   ap, bv);
                mma16816(oa[nj*2+1], ap, bv + 2);
            }
        }
    }

    // lacc columns are identical; [0] = rowsum(row g), [2] = rowsum(row g+8)
    float inv0 = 1.f / lacc[0], inv1 = 1.f / lacc[2];
    uint32_t tb = (uint32_t)(((b * 16 + qt) * 32 + h) * 16384);
    uint32_t* y32 = (uint32_t*)yt;
    const int r0 = warp * 16 + g, r1 = r0 + 8;
#pragma unroll
    for (int nb = 0; nb < 8; nb++) {
        int d0 = nb * 8 + tc2;
        uint32_t off0 = (uint32_t)(r0 * 128 + d0 * 2);
        uint32_t sw0  = off0 ^ ((off0 >> 3) & 0x70);
        y32[(tb + sw0) >> 2] = pack2h(oa[nb][0] * inv0, oa[nb][1] * inv0);
        uint32_t off1 = (uint32_t)(r1 * 128 + d0 * 2);
        uint32_t sw1  = off1 ^ ((off1 >> 3) & 0x70);
        y32[(tb + sw1) >> 2] = pack2h(oa[nb][2] * inv1, oa[nb][3] * inv1);
    }
}

// ---------------------------------------------------------------------------
extern "C" void kernel_launch(void* const* d_in, const int* in_sizes, int n_in,
                              void* d_out, int out_size)
{
    const float* x    = (const float*)d_in[0];
    const float* fcos = (const float*)d_in[1];
    const float* fsin = (const float*)d_in[2];
    const float* wq   = (const float*)d_in[3];
    const float* wk   = (const float*)d_in[4];
    const float* wv   = (const float*)d_in[5];
    const float* wo   = (const float*)d_in[6];
    float* out = (float*)d_out;

    uint4 *xt, *wqt, *wkt, *wvt, *wot;
    __half *qh, *kh, *vh;
    cudaGetSymbolAddress((void**)&xt, g_xt);
    cudaGetSymbolAddress((void**)&wqt, g_wqt);
    cudaGetSymbolAddress((void**)&wkt, g_wkt);
    cudaGetSymbolAddress((void**)&wvt, g_wvt);
    cudaGetSymbolAddress((void**)&wot, g_wot);
    cudaGetSymbolAddress((void**)&qh, g_qh);
    cudaGetSymbolAddress((void**)&kh, g_kh);
    cudaGetSymbolAddress((void**)&vh, g_vh);

    cudaFuncSetAttribute(hgemm, cudaFuncAttributeMaxDynamicSharedMemorySize, HG_SMEM);
    cudaFuncSetAttribute(attn,  cudaFuncAttributeMaxDynamicSharedMemorySize, AT_SMEM);

    dim3 cgrid(2048, 6);   // 4 weights + x (2 halves)
    conv_all<<<cgrid, 256>>>(wq, wk, wv, wo, x, wqt, wkt, wvt, wot, xt);

    dim3 ggrid3(Dd / 128, Mrows / 256, 3);   // fused QKV (16,16,3)
    hgemm<<<ggrid3, 256, HG_SMEM>>>(xt, wqt, wkt, wvt, nullptr,
                                    qh, kh, vh, fcos, fsin, 1);

    dim3 agrid(Tt / 128, Hh, Bb);            // (16, 32, 2)
    attn<<<agrid, 256, AT_SMEM>>>(qh, kh, vh, xt);

    dim3 ggrid(Dd / 128, Mrows / 256, 1);    // wo (16,16)
    hgemm<<<ggrid, 256, HG_SMEM>>>(xt, wot, nullptr, nullptr, out,
                                   nullptr, nullptr, nullptr, fcos, fsin, 0);
}

// round 15
// speedup vs baseline: 1.0454x; 1.0039x over previous
#include <cuda_runtime.h>
#include <cuda_fp16.h>
#include <cstdint>
#include <math.h>

#define Bb   2
#define Tt   2048
#define Dd   2048
#define Hh   32
#define HD   64
#define Mrows (Bb*Tt)          // 4096

// ---------------- scratch (__device__ globals) ------------------------------
__device__ uint4 g_xt [(size_t)1024*1024];     // A tiles (plain fp16): x, later y
__device__ uint4 g_wqt[(size_t)512*1024];      // W tiles (plain fp16)
__device__ uint4 g_wkt[(size_t)512*1024];
__device__ uint4 g_wvt[(size_t)512*1024];
__device__ uint4 g_wot[(size_t)512*1024];

// attention planes (plain fp16): Q,K [bh][t][d] ; V [bh][d][t]
__device__ __align__(16) __half g_qh[(size_t)64*2048*64];
__device__ __align__(16) __half g_kh[(size_t)64*2048*64];
__device__ __align__(16) __half g_vh[(size_t)64*2048*64];

// ---------------- PTX helpers ----------------------------------------------
__device__ __forceinline__ uint32_t smem_u32(const void* p) {
    return (uint32_t)__cvta_generic_to_shared(p);
}
__device__ __forceinline__ void mbar_init(uint32_t a, uint32_t cnt) {
    asm volatile("mbarrier.init.shared.b64 [%0], %1;" :: "r"(a), "r"(cnt) : "memory");
}
__device__ __forceinline__ void mbar_expect(uint32_t a, uint32_t tx) {
    asm volatile("mbarrier.arrive.expect_tx.shared.b64 _, [%0], %1;" :: "r"(a), "r"(tx) : "memory");
}
__device__ __forceinline__ void mbar_wait(uint32_t a, int parity) {
    asm volatile(
        "{\n\t.reg .pred P;\n\t"
        "WL_%=:\n\t"
        "mbarrier.try_wait.parity.acquire.cta.shared::cta.b64 P, [%0], %1, 0x989680;\n\t"
        "@P bra WD_%=;\n\t"
        "bra WL_%=;\n\t"
        "WD_%=:\n\t}"
        :: "r"(a), "r"(parity) : "memory");
}
__device__ __forceinline__ void bulk_g2s(uint32_t dst, const void* src, uint32_t bytes, uint32_t mbar) {
    asm volatile(
        "cp.async.bulk.shared::cluster.global.mbarrier::complete_tx::bytes [%0], [%1], %2, [%3];"
        :: "r"(dst), "l"(src), "r"(bytes), "r"(mbar) : "memory");
}
__device__ __forceinline__ void cpa16(uint32_t dst, const void* src) {
    asm volatile("cp.async.cg.shared.global [%0], [%1], 16;" :: "r"(dst), "l"(src) : "memory");
}
__device__ __forceinline__ void cpa_commit() {
    asm volatile("cp.async.commit_group;" ::: "memory");
}
__device__ __forceinline__ void ldmx4(uint32_t* r, uint32_t addr) {
    asm volatile("ldmatrix.sync.aligned.m8n8.x4.shared.b16 {%0,%1,%2,%3}, [%4];"
                 : "=r"(r[0]), "=r"(r[1]), "=r"(r[2]), "=r"(r[3]) : "r"(addr));
}
__device__ __forceinline__ void mma16816(float* d, const uint32_t* a, const uint32_t* b) {
    asm volatile(
        "mma.sync.aligned.m16n8k16.row.col.f32.f16.f16.f32 "
        "{%0,%1,%2,%3}, {%4,%5,%6,%7}, {%8,%9}, {%0,%1,%2,%3};"
        : "+f"(d[0]), "+f"(d[1]), "+f"(d[2]), "+f"(d[3])
        : "r"(a[0]), "r"(a[1]), "r"(a[2]), "r"(a[3]), "r"(b[0]), "r"(b[1]));
}
__device__ __forceinline__ uint32_t pack2h(float v0, float v1) {
    __half2 p = __float22half2_rn(make_float2(v0, v1));
    return *(uint32_t*)&p;
}
__device__ __forceinline__ uint32_t h2ex2(uint32_t x) {
    uint32_t y;
    asm("ex2.approx.f16x2 %0, %1;" : "=r"(y) : "r"(x));
    return y;
}

// ---------------------------------------------------------------------------
// Convert fp32 -> plain fp16, tiled 16KB chunks, SW128. One launch covers the
// 4 weights (grid.y 0..3) and x (grid.y 4..5). 4 rows per CTA (MLP=4).
// ---------------------------------------------------------------------------
__global__ __launch_bounds__(256) void conv_all(
    const float* __restrict__ w0, const float* __restrict__ w1,
    const float* __restrict__ w2, const float* __restrict__ w3,
    const float* __restrict__ xs,
    uint4* __restrict__ d0, uint4* __restrict__ d1,
    uint4* __restrict__ d2, uint4* __restrict__ d3,
    uint4* __restrict__ dx)
{
    const int which = blockIdx.y;
    const float* src;
    uint4* dst;
    if (which < 4) {
        src = which == 0 ? w0 : which == 1 ? w1 : which == 2 ? w2 : w3;
        dst = which == 0 ? d0 : which == 1 ? d1 : which == 2 ? d2 : d3;
    } else {
        src = xs + (size_t)(which - 4) * 2048 * Dd;
        dst = dx + (size_t)(which - 4) * 512 * 1024;
    }

    const int c8  = threadIdx.x;
    const int kc  = c8 >> 3;
    const int c16 = c8 & 7;

#pragma unroll
    for (int rr = 0; rr < 4; rr++) {
        int row = blockIdx.x * 4 + rr;
        const int nt = row >> 7, r = row & 127;

        const float4* s = (const float4*)(src + (size_t)row * Dd + c8 * 8);
        float4 f0 = s[0], f1 = s[1];
        float f[8] = {f0.x, f0.y, f0.z, f0.w, f1.x, f1.y, f1.z, f1.w};

        union { __half h[8]; uint4 v; } hv;
#pragma unroll
        for (int i = 0; i < 8; i++) hv.h[i] = __float2half(f[i]);

        uint32_t off = (uint32_t)(r * 128 + c16 * 16);
        uint32_t sw  = off ^ ((off >> 3) & 0x70);
        size_t tb = ((size_t)(nt * 32 + kc)) * 1024;
        dst[tb + sw / 16] = hv.v;
    }
}

// ---------------------------------------------------------------------------
// HMMA GEMM, plain fp16, CTA tile 256x128, warp tile 64x64 (4x2 warps), occ 1.
// 3-stage pipeline, 48KB stages (A = two 16KB chunks + B 16KB).
// fused=1: blockIdx.z -> {Q(mode1: RoPE+pre-scale), K(mode3: RoPE), V(mode2)}
// fused=0: fp32 C (wo). Epilogues smem-staged for coalesced writes.
// ---------------------------------------------------------------------------
#define HG_STAGE 49152
#define HG_SMEM  (2048 + 3 * HG_STAGE)   // ~146KB

__global__ __launch_bounds__(256, 1) void hgemm(
    const uint4* __restrict__ At,
    const uint4* __restrict__ W0, const uint4* __restrict__ W1,
    const uint4* __restrict__ W2,
    float* __restrict__ C,
    __half* __restrict__ qH, __half* __restrict__ kH, __half* __restrict__ vH,
    const float* __restrict__ fcos, const float* __restrict__ fsin,
    int fused)
{
    extern __shared__ char smraw[];
    const uint32_t base = (smem_u32(smraw) + 1023u) & ~1023u;
    const int tid = threadIdx.x, warp = tid >> 5, lane = tid & 31;
    const int bn = blockIdx.x, bm = blockIdx.y;

    const uint4* Wt; int mode;
    if (fused) {
        int z = blockIdx.z;
        Wt = (z == 0) ? W0 : (z == 1) ? W1 : W2;
        mode = (z == 0) ? 1 : (z == 1) ? 3 : 2;
    } else { Wt = W0; mode = 0; }

    const int wm4 = (warp >> 1) * 64;
    const int wn2 = (warp & 1) * 64;
    const int rA0l = (wm4 & 127) + ((lane >> 3) & 1) * 8 + (lane & 7);
    const uint32_t abase = (uint32_t)((wm4 >> 7) * 16384);
    const int qhA = lane >> 4;
    const int rB0 = wn2 + (lane >> 4) * 8 + (lane & 7);
    const int qhB = (lane >> 3) & 1;

    float acc[4][8][4];
#pragma unroll
    for (int mi = 0; mi < 4; mi++)
#pragma unroll
        for (int nb = 0; nb < 8; nb++)
#pragma unroll
            for (int e = 0; e < 4; e++) acc[mi][nb][e] = 0.f;

    if (tid == 0) { mbar_init(base, 1); mbar_init(base + 8, 1); mbar_init(base + 16, 1); }
    __syncthreads();

    const uint32_t tiles = base + 1024;
    const int mt0 = bm * 2;
    if (tid == 0) {
#pragma unroll
        for (int s = 0; s < 2; s++) {
            mbar_expect(base + s * 8, HG_STAGE);
            uint32_t st = tiles + s * HG_STAGE;
            bulk_g2s(st,         At + (size_t)(mt0 * 32 + s) * 1024,       16384, base + s * 8);
            bulk_g2s(st + 16384, At + (size_t)((mt0 + 1) * 32 + s) * 1024, 16384, base + s * 8);
            bulk_g2s(st + 32768, Wt + (size_t)(bn * 32 + s) * 1024,        16384, base + s * 8);
        }
    }

    int ph[3] = {0, 0, 0};
    for (int i = 0; i < 32; i++) {
        const int s = i % 3;
        if (tid == 0 && i + 2 < 32) {
            const int s2 = (i + 2) % 3;
            uint32_t full = base + s2 * 8;
            uint32_t st2  = tiles + s2 * HG_STAGE;
            mbar_expect(full, HG_STAGE);
            bulk_g2s(st2,         At + (size_t)(mt0 * 32 + i + 2) * 1024,       16384, full);
            bulk_g2s(st2 + 16384, At + (size_t)((mt0 + 1) * 32 + i + 2) * 1024, 16384, full);
            bulk_g2s(st2 + 32768, Wt + (size_t)(bn * 32 + i + 2) * 1024,        16384, full);
        }
        mbar_wait(base + s * 8, ph[s]); ph[s] ^= 1;

        const uint32_t stg = tiles + s * HG_STAGE;
        const uint32_t sA = stg + abase, sB = stg + 32768;

#pragma unroll
        for (int ks = 0; ks < 4; ks++) {
            uint32_t af[4][4], bf[8][2];
#pragma unroll
            for (int mi = 0; mi < 4; mi++) {
                int row = rA0l + mi * 16;
                uint32_t off = (uint32_t)(row * 128) + (uint32_t)(((ks * 2 + qhA) ^ (row & 7)) << 4);
                ldmx4(af[mi], sA + off);
            }
#pragma unroll
            for (int nj = 0; nj < 4; nj++) {
                int row = rB0 + nj * 16;
                uint32_t off = (uint32_t)(row * 128) + (uint32_t)(((ks * 2 + qhB) ^ (row & 7)) << 4);
                uint32_t t[4];
                ldmx4(t, sB + off);
                bf[nj*2][0] = t[0]; bf[nj*2][1] = t[1];
                bf[nj*2+1][0] = t[2]; bf[nj*2+1][1] = t[3];
            }
#pragma unroll
            for (int mi = 0; mi < 4; mi++)
#pragma unroll
                for (int nb = 0; nb < 8; nb++)
                    mma16816(acc[mi][nb], af[mi], bf[nb]);
        }
        __syncthreads();
    }

    // ---- epilogues
    char* smgen = smraw + (int)(tiles - smem_u32(smraw));
    const int bb = (bm * 256) >> 11;
    const int t0 = (bm * 256) & (Tt - 1);

    if (mode == 2) {
        __half* hs = (__half*)smgen;   // stride 264
#pragma unroll
        for (int mi = 0; mi < 4; mi++)
#pragma unroll
            for (int nb = 0; nb < 8; nb++) {
                int jl = wn2 + (lane & 3) * 2 + nb * 8;
#pragma unroll
                for (int half = 0; half < 2; half++) {
                    int ml = wm4 + (lane >> 2) + mi * 16 + half * 8;
                    hs[jl * 264 + ml]       = __float2half(acc[mi][nb][half * 2 + 0]);
                    hs[(jl + 1) * 264 + ml] = __float2half(acc[mi][nb][half * 2 + 1]);
                }
            }
        __syncthreads();
        for (int L = tid; L < 512; L += 256) {
            int j = L >> 2, part = L & 3;
            int d = bn * 128 + j, hh = d >> 6, dd = d & 63;
            __half* dst = vH + ((size_t)(bb * Hh + hh) * HD + dd) * Tt + t0 + part * 64;
            const uint4* srcv = (const uint4*)(hs + j * 264 + part * 64);
#pragma unroll
            for (int u = 0; u < 8; u++)
                *(uint4*)(dst + u * 8) = srcv[u];
        }
        return;
    }

    if (mode == 0) {
        float* sbf = (float*)smgen;   // [128][132]
#pragma unroll
        for (int p = 0; p < 2; p++) {
            if ((warp >> 2) == p) {
#pragma unroll
                for (int mi = 0; mi < 4; mi++)
#pragma unroll
                    for (int nb = 0; nb < 8; nb++) {
                        int jl = wn2 + (lane & 3) * 2 + nb * 8;
#pragma unroll
                        for (int half = 0; half < 2; half++) {
                            int ml = (wm4 & 127) + (lane >> 2) + mi * 16 + half * 8;
                            sbf[ml * 132 + jl]     = acc[mi][nb][half * 2 + 0];
                            sbf[ml * 132 + jl + 1] = acc[mi][nb][half * 2 + 1];
                        }
                    }
            }
            __syncthreads();
#pragma unroll
            for (int r = warp; r < 128; r += 8) {
                float4 v = *(const float4*)&sbf[r * 132 + lane * 4];
                *(float4*)(C + (size_t)(bm * 256 + p * 128 + r) * Dd + bn * 128 + lane * 4) = v;
            }
            __syncthreads();
        }
        return;
    }

    // modes 1 (Q, pre-scaled) and 3 (K): RoPE + stage packed u32 [256][66]
    {
        uint32_t* sb = (uint32_t*)smgen;
        const float SCQ = (mode == 1) ? 0.18033688f : 1.0f;  // (1/8)*log2(e)
#pragma unroll
        for (int mi = 0; mi < 4; mi++)
#pragma unroll
            for (int nb = 0; nb < 8; nb++) {
                int jl = wn2 + (lane & 3) * 2 + nb * 8;
                int pi = (jl & 63) >> 1;
#pragma unroll
                for (int half = 0; half < 2; half++) {
                    int ml = wm4 + (lane >> 2) + mi * 16 + half * 8;
                    int t  = (bm * 256 + ml) & (Tt - 1);
                    float cv = fcos[t * (HD / 2) + pi], sv = fsin[t * (HD / 2) + pi];
                    float v0 = acc[mi][nb][half * 2 + 0];
                    float v1 = acc[mi][nb][half * 2 + 1];
                    float r0 = (v0 * cv - v1 * sv) * SCQ;
                    float i0 = (v0 * sv + v1 * cv) * SCQ;
                    sb[ml * 66 + (jl >> 1)] = pack2h(r0, i0);
                }
            }
        __syncthreads();
        int hh0 = bn * 2;
        uint32_t* dstp = (uint32_t*)((mode == 1) ? qH : kH);
        for (int L = warp; L < 512; L += 8) {
            int row = L >> 1;
            int hh  = L & 1;
            uint32_t val = sb[row * 66 + hh * 32 + lane];
            dstp[((size_t)(bb * Hh + hh0 + hh) * Tt + t0 + row) * 32 + lane] = val;
        }
    }
}

// ---------------------------------------------------------------------------
// Tensor-core flash attention, fixed-shift softmax, l-sums via ones-MMA,
// exp via ex2.approx.f16x2 (pack S to fp16 pairs, then one MUFU op per pair).
// Single-pass S and PV, 3-stage cp.async pipeline, 1 sync/iter.
// smem: Q 16K | 3 stages x (K 8K | V 8K) = 64KB.
// ---------------------------------------------------------------------------
#define AT_SMEM (16384 + 3 * 16384)

__global__ __launch_bounds__(256, 2) void attn(
    const __half* __restrict__ qh,
    const __half* __restrict__ kh, const __half* __restrict__ vh,
    uint4* __restrict__ yt)
{
    extern __shared__ char smraw[];
    const uint32_t smb = smem_u32(smraw);
    const int tid = threadIdx.x, warp = tid >> 5, lane = tid & 31;
    const int qt = (int)gridDim.x - 1 - (int)blockIdx.x;
    const int h  = blockIdx.y, b = blockIdx.z;
    const int bh = b * Hh + h;
    const int ktmax = 2 * qt + 2;

    // ---- group 0: Q into smem (128 rows; 2 threads per row)
    {
        int r = tid >> 1, half = tid & 1;
        const __half* src = qh + ((size_t)bh * Tt + qt * 128 + r) * HD;
        uint32_t dst = smb + r * 128;
#pragma unroll
        for (int cc = 0; cc < 4; cc++) {
            int c = half * 4 + cc;
            cpa16(dst + (uint32_t)(((c ^ (r & 7)) << 4)), src + c * 8);
        }
    }
    cpa_commit();
    // ---- stage loader geometry
    const int srow = tid >> 1, shalf = tid & 1;
#pragma unroll
    for (int s0 = 0; s0 < 2; s0++) {
        uint32_t dst; const __half* src;
        uint32_t sbase = smb + 16384 + (uint32_t)(s0 * 16384);
        if (srow < 64) {
            dst = sbase + srow * 128;
            src = kh + ((size_t)bh * Tt + s0 * 64 + srow) * HD;
        } else {
            int d = srow - 64;
            dst = sbase + 8192 + d * 128;
            src = vh + ((size_t)bh * HD + d) * Tt + s0 * 64;
        }
#pragma unroll
        for (int cc = 0; cc < 4; cc++) {
            int c = shalf * 4 + cc;
            cpa16(dst + (uint32_t)(((c ^ (srow & 7)) << 4)), src + c * 8);
        }
        cpa_commit();
    }

    const int g    = lane >> 2;
    const int tc2  = (lane & 3) * 2;
    const int rA0  = warp * 16 + ((lane >> 3) & 1) * 8 + (lane & 7);
    const int qhA  = lane >> 4;
    const int rB0  = (lane >> 4) * 8 + (lane & 7);
    const int qhB  = (lane >> 3) & 1;
    const int row0g = qt * 128 + warp * 16 + g;

    // ---- hoist Q fragments into registers
    uint32_t qf[4][4];
    asm volatile("cp.async.wait_group 2;" ::: "memory");
    __syncthreads();
#pragma unroll
    for (int kg = 0; kg < 4; kg++) {
        uint32_t offA = (uint32_t)(rA0 * 128) + (uint32_t)(((kg * 2 + qhA) ^ (rA0 & 7)) << 4);
        ldmx4(qf[kg], smb + offA);
    }

    float oa[8][4];
#pragma unroll
    for (int nb = 0; nb < 8; nb++)
#pragma unroll
        for (int e = 0; e < 4; e++) oa[nb][e] = 0.f;
    float lacc[4] = {0.f, 0.f, 0.f, 0.f};           // ones-MMA row-sum acc
    const uint32_t bones[2] = {0x3C003C00u, 0x3C003C00u};  // fp16 1.0 frag

    for (int kt = 0; kt < ktmax; kt++) {
        const uint32_t stage = smb + 16384 + (uint32_t)((kt % 3) * 16384);
        asm volatile("cp.async.wait_group 1;" ::: "memory");
        __syncthreads();

        if (kt + 2 < ktmax) {
            uint32_t sbase = smb + 16384 + (uint32_t)(((kt + 2) % 3) * 16384);
            uint32_t dst; const __half* src;
            if (srow < 64) {
                dst = sbase + srow * 128;
                src = kh + ((size_t)bh * Tt + (kt + 2) * 64 + srow) * HD;
            } else {
                int d = srow - 64;
                dst = sbase + 8192 + d * 128;
                src = vh + ((size_t)bh * HD + d) * Tt + (kt + 2) * 64;
            }
#pragma unroll
            for (int cc = 0; cc < 4; cc++) {
                int c = shalf * 4 + cc;
                cpa16(dst + (uint32_t)(((c ^ (srow & 7)) << 4)), src + c * 8);
            }
        }
        cpa_commit();

        // ---- S = Q K^T (single pass; Q pre-scaled into log2 units)
        float sa[8][4];
#pragma unroll
        for (int nb = 0; nb < 8; nb++)
#pragma unroll
            for (int e = 0; e < 4; e++) sa[nb][e] = 0.f;

#pragma unroll
        for (int kg = 0; kg < 4; kg++) {
#pragma unroll
            for (int nj = 0; nj < 4; nj++) {
                int rB = rB0 + nj * 16;
                uint32_t offB = (uint32_t)(rB * 128) + (uint32_t)(((kg * 2 + qhB) ^ (rB & 7)) << 4);
                uint32_t th[4];
                ldmx4(th, stage + offB);
                mma16816(sa[nj*2],   qf[kg], th);
                mma16816(sa[nj*2+1], qf[kg], th + 2);
            }
        }

        // ---- causal mask (masked -> -1e30 -> fp16 -inf -> exp 0)
        const bool dm = (kt >= 2 * qt);
        if (dm) {
#pragma unroll
            for (int nb = 0; nb < 8; nb++) {
                int colb = kt * 64 + nb * 8 + tc2;
                if (colb     > row0g)     sa[nb][0] = -1e30f;
                if (colb + 1 > row0g)     sa[nb][1] = -1e30f;
                if (colb     > row0g + 8) sa[nb][2] = -1e30f;
                if (colb + 1 > row0g + 8) sa[nb][3] = -1e30f;
            }
        }

        // ---- O += P V; l += P @ ones. P = ex2.f16x2(pack(S)) — 1 MUFU/pair.
#pragma unroll
        for (int kg = 0; kg < 4; kg++) {
            float* c0 = sa[2 * kg];
            float* c1 = sa[2 * kg + 1];
            uint32_t ap[4];
            ap[0] = h2ex2(pack2h(c0[0], c0[1]));
            ap[1] = h2ex2(pack2h(c0[2], c0[3]));
            ap[2] = h2ex2(pack2h(c1[0], c1[1]));
            ap[3] = h2ex2(pack2h(c1[2], c1[3]));
            mma16816(lacc, ap, bones);
#pragma unroll
            for (int nj = 0; nj < 4; nj++) {
                int rB = rB0 + nj * 16;
                uint32_t offB = (uint32_t)(rB * 128) + (uint32_t)(((kg * 2 + qhB) ^ (rB & 7)) << 4);
                uint32_t bv[4];
                ldmx4(bv, stage + 8192 + offB);
                mma16816(oa[nj*2],   ap, bv);
                mma16816(oa[nj*2+1], ap, bv + 2);
            }
        }
    }

    // lacc columns are identical; [0] = rowsum(row g), [2] = rowsum(row g+8)
    float inv0 = 1.f / lacc[0], inv1 = 1.f / lacc[2];
    uint32_t tb = (uint32_t)(((b * 16 + qt) * 32 + h) * 16384);
    uint32_t* y32 = (uint32_t*)yt;
    const int r0 = warp * 16 + g, r1 = r0 + 8;
#pragma unroll
    for (int nb = 0; nb < 8; nb++) {
        int d0 = nb * 8 + tc2;
        uint32_t off0 = (uint32_t)(r0 * 128 + d0 * 2);
        uint32_t sw0  = off0 ^ ((off0 >> 3) & 0x70);
        y32[(tb + sw0) >> 2] = pack2h(oa[nb][0] * inv0, oa[nb][1] * inv0);
        uint32_t off1 = (uint32_t)(r1 * 128 + d0 * 2);
        uint32_t sw1  = off1 ^ ((off1 >> 3) & 0x70);
        y32[(tb + sw1) >> 2] = pack2h(oa[nb][2] * inv1, oa[nb][3] * inv1);
    }
}

// ---------------------------------------------------------------------------
extern "C" void kernel_launch(void* const* d_in, const int* in_sizes, int n_in,
                              void* d_out, int out_size)
{
    const float* x    = (const float*)d_in[0];
    const float* fcos = (const float*)d_in[1];
    const float* fsin = (const float*)d_in[2];
    const float* wq   = (const float*)d_in[3];
    const float* wk   = (const float*)d_in[4];
    const float* wv   = (const float*)d_in[5];
    const float* wo   = (const float*)d_in[6];
    float* out = (float*)d_out;

    uint4 *xt, *wqt, *wkt, *wvt, *wot;
    __half *qh, *kh, *vh;
    cudaGetSymbolAddress((void**)&xt, g_xt);
    cudaGetSymbolAddress((void**)&wqt, g_wqt);
    cudaGetSymbolAddress((void**)&wkt, g_wkt);
    cudaGetSymbolAddress((void**)&wvt, g_wvt);
    cudaGetSymbolAddress((void**)&wot, g_wot);
    cudaGetSymbolAddress((void**)&qh, g_qh);
    cudaGetSymbolAddress((void**)&kh, g_kh);
    cudaGetSymbolAddress((void**)&vh, g_vh);

    cudaFuncSetAttribute(hgemm, cudaFuncAttributeMaxDynamicSharedMemorySize, HG_SMEM);
    cudaFuncSetAttribute(attn,  cudaFuncAttributeMaxDynamicSharedMemorySize, AT_SMEM);

    dim3 cgrid(512, 6);    // 4 weights + x (2 halves), 4 rows per CTA
    conv_all<<<cgrid, 256>>>(wq, wk, wv, wo, x, wqt, wkt, wvt, wot, xt);

    dim3 ggrid3(Dd / 128, Mrows / 256, 3);   // fused QKV (16,16,3)
    hgemm<<<ggrid3, 256, HG_SMEM>>>(xt, wqt, wkt, wvt, nullptr,
                                    qh, kh, vh, fcos, fsin, 1);

    dim3 agrid(Tt / 128, Hh, Bb);            // (16, 32, 2)
    attn<<<agrid, 256, AT_SMEM>>>(qh, kh, vh, xt);

    dim3 ggrid(Dd / 128, Mrows / 256, 1);    // wo (16,16)
    hgemm<<<ggrid, 256, HG_SMEM>>>(xt, wot, nullptr, nullptr, out,
                                   nullptr, nullptr, nullptr, fcos, fsin, 0);
}

// round 16
// speedup vs baseline: 1.0904x; 1.0430x over previous
#include <cuda_runtime.h>
#include <cuda_fp16.h>
#include <cstdint>
#include <math.h>

#define Bb   2
#define Tt   2048
#define Dd   2048
#define Hh   32
#define HD   64
#define Mrows (Bb*Tt)          // 4096

// ---------------- scratch (__device__ globals) ------------------------------
__device__ uint4 g_xt [(size_t)1024*1024];     // A tiles (plain fp16): x, later y
__device__ uint4 g_wqt[(size_t)512*1024];      // W tiles (plain fp16)
__device__ uint4 g_wkt[(size_t)512*1024];
__device__ uint4 g_wvt[(size_t)512*1024];
__device__ uint4 g_wot[(size_t)512*1024];

// attention planes (plain fp16): Q,K [bh][t][d] ; V [bh][d][t]
__device__ __align__(16) __half g_qh[(size_t)64*2048*64];
__device__ __align__(16) __half g_kh[(size_t)64*2048*64];
__device__ __align__(16) __half g_vh[(size_t)64*2048*64];

// ---------------- PTX helpers ----------------------------------------------
__device__ __forceinline__ uint32_t smem_u32(const void* p) {
    return (uint32_t)__cvta_generic_to_shared(p);
}
__device__ __forceinline__ void mbar_init(uint32_t a, uint32_t cnt) {
    asm volatile("mbarrier.init.shared.b64 [%0], %1;" :: "r"(a), "r"(cnt) : "memory");
}
__device__ __forceinline__ void mbar_expect(uint32_t a, uint32_t tx) {
    asm volatile("mbarrier.arrive.expect_tx.shared.b64 _, [%0], %1;" :: "r"(a), "r"(tx) : "memory");
}
__device__ __forceinline__ void mbar_arrive(uint32_t a) {
    asm volatile("mbarrier.arrive.shared.b64 _, [%0];" :: "r"(a) : "memory");
}
__device__ __forceinline__ void mbar_wait(uint32_t a, int parity) {
    asm volatile(
        "{\n\t.reg .pred P;\n\t"
        "WL_%=:\n\t"
        "mbarrier.try_wait.parity.acquire.cta.shared::cta.b64 P, [%0], %1, 0x989680;\n\t"
        "@P bra WD_%=;\n\t"
        "bra WL_%=;\n\t"
        "WD_%=:\n\t}"
        :: "r"(a), "r"(parity) : "memory");
}
__device__ __forceinline__ void bulk_g2s(uint32_t dst, const void* src, uint32_t bytes, uint32_t mbar) {
    asm volatile(
        "cp.async.bulk.shared::cluster.global.mbarrier::complete_tx::bytes [%0], [%1], %2, [%3];"
        :: "r"(dst), "l"(src), "r"(bytes), "r"(mbar) : "memory");
}
__device__ __forceinline__ void cpa16(uint32_t dst, const void* src) {
    asm volatile("cp.async.cg.shared.global [%0], [%1], 16;" :: "r"(dst), "l"(src) : "memory");
}
__device__ __forceinline__ void cpa_commit() {
    asm volatile("cp.async.commit_group;" ::: "memory");
}
__device__ __forceinline__ void ldmx4(uint32_t* r, uint32_t addr) {
    asm volatile("ldmatrix.sync.aligned.m8n8.x4.shared.b16 {%0,%1,%2,%3}, [%4];"
                 : "=r"(r[0]), "=r"(r[1]), "=r"(r[2]), "=r"(r[3]) : "r"(addr));
}
__device__ __forceinline__ void mma16816(float* d, const uint32_t* a, const uint32_t* b) {
    asm volatile(
        "mma.sync.aligned.m16n8k16.row.col.f32.f16.f16.f32 "
        "{%0,%1,%2,%3}, {%4,%5,%6,%7}, {%8,%9}, {%0,%1,%2,%3};"
        : "+f"(d[0]), "+f"(d[1]), "+f"(d[2]), "+f"(d[3])
        : "r"(a[0]), "r"(a[1]), "r"(a[2]), "r"(a[3]), "r"(b[0]), "r"(b[1]));
}
__device__ __forceinline__ uint32_t pack2h(float v0, float v1) {
    __half2 p = __float22half2_rn(make_float2(v0, v1));
    return *(uint32_t*)&p;
}
__device__ __forceinline__ uint32_t h2ex2(uint32_t x) {
    uint32_t y;
    asm("ex2.approx.f16x2 %0, %1;" : "=r"(y) : "r"(x));
    return y;
}

// ---------------------------------------------------------------------------
// Convert fp32 -> plain fp16, tiled 16KB chunks, SW128. One launch covers the
// 4 weights (grid.y 0..3) and x (grid.y 4..5). 4 rows per CTA (MLP=4).
// ---------------------------------------------------------------------------
__global__ __launch_bounds__(256) void conv_all(
    const float* __restrict__ w0, const float* __restrict__ w1,
    const float* __restrict__ w2, const float* __restrict__ w3,
    const float* __restrict__ xs,
    uint4* __restrict__ d0, uint4* __restrict__ d1,
    uint4* __restrict__ d2, uint4* __restrict__ d3,
    uint4* __restrict__ dx)
{
    const int which = blockIdx.y;
    const float* src;
    uint4* dst;
    if (which < 4) {
        src = which == 0 ? w0 : which == 1 ? w1 : which == 2 ? w2 : w3;
        dst = which == 0 ? d0 : which == 1 ? d1 : which == 2 ? d2 : d3;
    } else {
        src = xs + (size_t)(which - 4) * 2048 * Dd;
        dst = dx + (size_t)(which - 4) * 512 * 1024;
    }

    const int c8  = threadIdx.x;
    const int kc  = c8 >> 3;
    const int c16 = c8 & 7;

#pragma unroll
    for (int rr = 0; rr < 4; rr++) {
        int row = blockIdx.x * 4 + rr;
        const int nt = row >> 7, r = row & 127;

        const float4* s = (const float4*)(src + (size_t)row * Dd + c8 * 8);
        float4 f0 = s[0], f1 = s[1];
        float f[8] = {f0.x, f0.y, f0.z, f0.w, f1.x, f1.y, f1.z, f1.w};

        union { __half h[8]; uint4 v; } hv;
#pragma unroll
        for (int i = 0; i < 8; i++) hv.h[i] = __float2half(f[i]);

        uint32_t off = (uint32_t)(r * 128 + c16 * 16);
        uint32_t sw  = off ^ ((off >> 3) & 0x70);
        size_t tb = ((size_t)(nt * 32 + kc)) * 1024;
        dst[tb + sw / 16] = hv.v;
    }
}

// ---------------------------------------------------------------------------
// HMMA GEMM, plain fp16, CTA tile 256x128, warp tile 64x64 (4x2 warps), occ 1.
// 3-stage pipeline with producer/consumer mbarriers, NO per-iter syncthreads:
//   full[s]  (count 1, tx)      : stage filled
//   empty[s] (count 8, arrive)  : all 8 warps done reading stage
// Warps skew freely (bounded by the 3-stage ring).
// fused=1: blockIdx.z -> {Q(mode1: RoPE+pre-scale), K(mode3: RoPE), V(mode2)}
// fused=0: fp32 C (wo). Epilogues smem-staged for coalesced writes.
// ---------------------------------------------------------------------------
#define HG_STAGE 49152
#define HG_SMEM  (2048 + 3 * HG_STAGE)   // ~146KB

__global__ __launch_bounds__(256, 1) void hgemm(
    const uint4* __restrict__ At,
    const uint4* __restrict__ W0, const uint4* __restrict__ W1,
    const uint4* __restrict__ W2,
    float* __restrict__ C,
    __half* __restrict__ qH, __half* __restrict__ kH, __half* __restrict__ vH,
    const float* __restrict__ fcos, const float* __restrict__ fsin,
    int fused)
{
    extern __shared__ char smraw[];
    const uint32_t base = (smem_u32(smraw) + 1023u) & ~1023u;
    const int tid = threadIdx.x, warp = tid >> 5, lane = tid & 31;
    const int bn = blockIdx.x, bm = blockIdx.y;

    const uint4* Wt; int mode;
    if (fused) {
        int z = blockIdx.z;
        Wt = (z == 0) ? W0 : (z == 1) ? W1 : W2;
        mode = (z == 0) ? 1 : (z == 1) ? 3 : 2;
    } else { Wt = W0; mode = 0; }

    const int wm4 = (warp >> 1) * 64;
    const int wn2 = (warp & 1) * 64;
    const int rA0l = (wm4 & 127) + ((lane >> 3) & 1) * 8 + (lane & 7);
    const uint32_t abase = (uint32_t)((wm4 >> 7) * 16384);
    const int qhA = lane >> 4;
    const int rB0 = wn2 + (lane >> 4) * 8 + (lane & 7);
    const int qhB = (lane >> 3) & 1;

    float acc[4][8][4];
#pragma unroll
    for (int mi = 0; mi < 4; mi++)
#pragma unroll
        for (int nb = 0; nb < 8; nb++)
#pragma unroll
            for (int e = 0; e < 4; e++) acc[mi][nb][e] = 0.f;

    // full[s] @ base + s*8 (count 1); empty[s] @ base + 64 + s*8 (count 8)
    if (tid == 0) {
#pragma unroll
        for (int s = 0; s < 3; s++) { mbar_init(base + s * 8, 1); mbar_init(base + 64 + s * 8, 8); }
    }
    __syncthreads();

    const uint32_t tiles = base + 1024;
    const int mt0 = bm * 2;
    if (tid == 0) {
#pragma unroll
        for (int s = 0; s < 2; s++) {
            mbar_expect(base + s * 8, HG_STAGE);
            uint32_t st = tiles + s * HG_STAGE;
            bulk_g2s(st,         At + (size_t)(mt0 * 32 + s) * 1024,       16384, base + s * 8);
            bulk_g2s(st + 16384, At + (size_t)((mt0 + 1) * 32 + s) * 1024, 16384, base + s * 8);
            bulk_g2s(st + 32768, Wt + (size_t)(bn * 32 + s) * 1024,        16384, base + s * 8);
        }
    }

    int ph[3]  = {0, 0, 0};   // per-warp full phases
    int eph[3] = {0, 0, 0};   // producer-side empty phases (tid0 only)
    for (int i = 0; i < 32; i++) {
        const int s = i % 3;
        if (tid == 0 && i + 2 < 32) {
            const int s2 = (i + 2) % 3;
            if (i >= 1) { mbar_wait(base + 64 + s2 * 8, eph[s2]); eph[s2] ^= 1; }
            uint32_t full = base + s2 * 8;
            uint32_t st2  = tiles + s2 * HG_STAGE;
            mbar_expect(full, HG_STAGE);
            bulk_g2s(st2,         At + (size_t)(mt0 * 32 + i + 2) * 1024,       16384, full);
            bulk_g2s(st2 + 16384, At + (size_t)((mt0 + 1) * 32 + i + 2) * 1024, 16384, full);
            bulk_g2s(st2 + 32768, Wt + (size_t)(bn * 32 + i + 2) * 1024,        16384, full);
        }
        mbar_wait(base + s * 8, ph[s]); ph[s] ^= 1;

        const uint32_t stg = tiles + s * HG_STAGE;
        const uint32_t sA = stg + abase, sB = stg + 32768;

#pragma unroll
        for (int ks = 0; ks < 4; ks++) {
            uint32_t af[4][4], bf[8][2];
#pragma unroll
            for (int mi = 0; mi < 4; mi++) {
                int row = rA0l + mi * 16;
                uint32_t off = (uint32_t)(row * 128) + (uint32_t)(((ks * 2 + qhA) ^ (row & 7)) << 4);
                ldmx4(af[mi], sA + off);
            }
#pragma unroll
            for (int nj = 0; nj < 4; nj++) {
                int row = rB0 + nj * 16;
                uint32_t off = (uint32_t)(row * 128) + (uint32_t)(((ks * 2 + qhB) ^ (row & 7)) << 4);
                uint32_t t[4];
                ldmx4(t, sB + off);
                bf[nj*2][0] = t[0]; bf[nj*2][1] = t[1];
                bf[nj*2+1][0] = t[2]; bf[nj*2+1][1] = t[3];
            }
#pragma unroll
            for (int mi = 0; mi < 4; mi++)
#pragma unroll
                for (int nb = 0; nb < 8; nb++)
                    mma16816(acc[mi][nb], af[mi], bf[nb]);
        }
        if (lane == 0) mbar_arrive(base + 64 + s * 8);   // this warp done with stage s
    }
    __syncthreads();   // all warps out of the mainloop before epilogue smem reuse

    // ---- epilogues
    char* smgen = smraw + (int)(tiles - smem_u32(smraw));
    const int bb = (bm * 256) >> 11;
    const int t0 = (bm * 256) & (Tt - 1);

    if (mode == 2) {
        __half* hs = (__half*)smgen;   // stride 264
#pragma unroll
        for (int mi = 0; mi < 4; mi++)
#pragma unroll
            for (int nb = 0; nb < 8; nb++) {
                int jl = wn2 + (lane & 3) * 2 + nb * 8;
#pragma unroll
                for (int half = 0; half < 2; half++) {
                    int ml = wm4 + (lane >> 2) + mi * 16 + half * 8;
                    hs[jl * 264 + ml]       = __float2half(acc[mi][nb][half * 2 + 0]);
                    hs[(jl + 1) * 264 + ml] = __float2half(acc[mi][nb][half * 2 + 1]);
                }
            }
        __syncthreads();
        for (int L = tid; L < 512; L += 256) {
            int j = L >> 2, part = L & 3;
            int d = bn * 128 + j, hh = d >> 6, dd = d & 63;
            __half* dst = vH + ((size_t)(bb * Hh + hh) * HD + dd) * Tt + t0 + part * 64;
            const uint4* srcv = (const uint4*)(hs + j * 264 + part * 64);
#pragma unroll
            for (int u = 0; u < 8; u++)
                *(uint4*)(dst + u * 8) = srcv[u];
        }
        return;
    }

    if (mode == 0) {
        float* sbf = (float*)smgen;   // [128][132]
#pragma unroll
        for (int p = 0; p < 2; p++) {
            if ((warp >> 2) == p) {
#pragma unroll
                for (int mi = 0; mi < 4; mi++)
#pragma unroll
                    for (int nb = 0; nb < 8; nb++) {
                        int jl = wn2 + (lane & 3) * 2 + nb * 8;
#pragma unroll
                        for (int half = 0; half < 2; half++) {
                            int ml = (wm4 & 127) + (lane >> 2) + mi * 16 + half * 8;
                            sbf[ml * 132 + jl]     = acc[mi][nb][half * 2 + 0];
                            sbf[ml * 132 + jl + 1] = acc[mi][nb][half * 2 + 1];
                        }
                    }
            }
            __syncthreads();
#pragma unroll
            for (int r = warp; r < 128; r += 8) {
                float4 v = *(const float4*)&sbf[r * 132 + lane * 4];
                *(float4*)(C + (size_t)(bm * 256 + p * 128 + r) * Dd + bn * 128 + lane * 4) = v;
            }
            __syncthreads();
        }
        return;
    }

    // modes 1 (Q, pre-scaled) and 3 (K): RoPE + stage packed u32 [256][66]
    {
        uint32_t* sb = (uint32_t*)smgen;
        const float SCQ = (mode == 1) ? 0.18033688f : 1.0f;  // (1/8)*log2(e)
#pragma unroll
        for (int mi = 0; mi < 4; mi++)
#pragma unroll
            for (int nb = 0; nb < 8; nb++) {
                int jl = wn2 + (lane & 3) * 2 + nb * 8;
                int pi = (jl & 63) >> 1;
#pragma unroll
                for (int half = 0; half < 2; half++) {
                    int ml = wm4 + (lane >> 2) + mi * 16 + half * 8;
                    int t  = (bm * 256 + ml) & (Tt - 1);
                    float cv = fcos[t * (HD / 2) + pi], sv = fsin[t * (HD / 2) + pi];
                    float v0 = acc[mi][nb][half * 2 + 0];
                    float v1 = acc[mi][nb][half * 2 + 1];
                    float r0 = (v0 * cv - v1 * sv) * SCQ;
                    float i0 = (v0 * sv + v1 * cv) * SCQ;
                    sb[ml * 66 + (jl >> 1)] = pack2h(r0, i0);
                }
            }
        __syncthreads();
        int hh0 = bn * 2;
        uint32_t* dstp = (uint32_t*)((mode == 1) ? qH : kH);
        for (int L = warp; L < 512; L += 8) {
            int row = L >> 1;
            int hh  = L & 1;
            uint32_t val = sb[row * 66 + hh * 32 + lane];
            dstp[((size_t)(bb * Hh + hh0 + hh) * Tt + t0 + row) * 32 + lane] = val;
        }
    }
}

// ---------------------------------------------------------------------------
// Tensor-core flash attention, fixed-shift softmax, l-sums via ones-MMA,
// exp via ex2.approx.f16x2. Single-pass S and PV, 3-stage cp.async pipeline.
// smem: Q 16K | 3 stages x (K 8K | V 8K) = 64KB.
// ---------------------------------------------------------------------------
#define AT_SMEM (16384 + 3 * 16384)

__global__ __launch_bounds__(256, 2) void attn(
    const __half* __restrict__ qh,
    const __half* __restrict__ kh, const __half* __restrict__ vh,
    uint4* __restrict__ yt)
{
    extern __shared__ char smraw[];
    const uint32_t smb = smem_u32(smraw);
    const int tid = threadIdx.x, warp = tid >> 5, lane = tid & 31;
    const int qt = (int)gridDim.x - 1 - (int)blockIdx.x;
    const int h  = blockIdx.y, b = blockIdx.z;
    const int bh = b * Hh + h;
    const int ktmax = 2 * qt + 2;

    // ---- group 0: Q into smem (128 rows; 2 threads per row)
    {
        int r = tid >> 1, half = tid & 1;
        const __half* src = qh + ((size_t)bh * Tt + qt * 128 + r) * HD;
        uint32_t dst = smb + r * 128;
#pragma unroll
        for (int cc = 0; cc < 4; cc++) {
            int c = half * 4 + cc;
            cpa16(dst + (uint32_t)(((c ^ (r & 7)) << 4)), src + c * 8);
        }
    }
    cpa_commit();
    // ---- stage loader geometry
    const int srow = tid >> 1, shalf = tid & 1;
#pragma unroll
    for (int s0 = 0; s0 < 2; s0++) {
        uint32_t dst; const __half* src;
        uint32_t sbase = smb + 16384 + (uint32_t)(s0 * 16384);
        if (srow < 64) {
            dst = sbase + srow * 128;
            src = kh + ((size_t)bh * Tt + s0 * 64 + srow) * HD;
        } else {
            int d = srow - 64;
            dst = sbase + 8192 + d * 128;
            src = vh + ((size_t)bh * HD + d) * Tt + s0 * 64;
        }
#pragma unroll
        for (int cc = 0; cc < 4; cc++) {
            int c = shalf * 4 + cc;
            cpa16(dst + (uint32_t)(((c ^ (srow & 7)) << 4)), src + c * 8);
        }
        cpa_commit();
    }

    const int g    = lane >> 2;
    const int tc2  = (lane & 3) * 2;
    const int rA0  = warp * 16 + ((lane >> 3) & 1) * 8 + (lane & 7);
    const int qhA  = lane >> 4;
    const int rB0  = (lane >> 4) * 8 + (lane & 7);
    const int qhB  = (lane >> 3) & 1;
    const int row0g = qt * 128 + warp * 16 + g;

    // ---- hoist Q fragments into registers
    uint32_t qf[4][4];
    asm volatile("cp.async.wait_group 2;" ::: "memory");
    __syncthreads();
#pragma unroll
    for (int kg = 0; kg < 4; kg++) {
        uint32_t offA = (uint32_t)(rA0 * 128) + (uint32_t)(((kg * 2 + qhA) ^ (rA0 & 7)) << 4);
        ldmx4(qf[kg], smb + offA);
    }

    float oa[8][4];
#pragma unroll
    for (int nb = 0; nb < 8; nb++)
#pragma unroll
        for (int e = 0; e < 4; e++) oa[nb][e] = 0.f;
    float lacc[4] = {0.f, 0.f, 0.f, 0.f};           // ones-MMA row-sum acc
    const uint32_t bones[2] = {0x3C003C00u, 0x3C003C00u};  // fp16 1.0 frag

    for (int kt = 0; kt < ktmax; kt++) {
        const uint32_t stage = smb + 16384 + (uint32_t)((kt % 3) * 16384);
        asm volatile("cp.async.wait_group 1;" ::: "memory");
        __syncthreads();

        if (kt + 2 < ktmax) {
            uint32_t sbase = smb + 16384 + (uint32_t)(((kt + 2) % 3) * 16384);
            uint32_t dst; const __half* src;
            if (srow < 64) {
                dst = sbase + srow * 128;
                src = kh + ((size_t)bh * Tt + (kt + 2) * 64 + srow) * HD;
            } else {
                int d = srow - 64;
                dst = sbase + 8192 + d * 128;
                src = vh + ((size_t)bh * HD + d) * Tt + (kt + 2) * 64;
            }
#pragma unroll
            for (int cc = 0; cc < 4; cc++) {
                int c = shalf * 4 + cc;
                cpa16(dst + (uint32_t)(((c ^ (srow & 7)) << 4)), src + c * 8);
            }
        }
        cpa_commit();

        // ---- S = Q K^T (single pass; Q pre-scaled into log2 units)
        float sa[8][4];
#pragma unroll
        for (int nb = 0; nb < 8; nb++)
#pragma unroll
            for (int e = 0; e < 4; e++) sa[nb][e] = 0.f;

#pragma unroll
        for (int kg = 0; kg < 4; kg++) {
#pragma unroll
            for (int nj = 0; nj < 4; nj++) {
                int rB = rB0 + nj * 16;
                uint32_t offB = (uint32_t)(rB * 128) + (uint32_t)(((kg * 2 + qhB) ^ (rB & 7)) << 4);
                uint32_t th[4];
                ldmx4(th, stage + offB);
                mma16816(sa[nj*2],   qf[kg], th);
                mma16816(sa[nj*2+1], qf[kg], th + 2);
            }
        }

        // ---- causal mask (masked -> -1e30 -> fp16 -inf -> exp 0)
        const bool dm = (kt >= 2 * qt);
        if (dm) {
#pragma unroll
            for (int nb = 0; nb < 8; nb++) {
                int colb = kt * 64 + nb * 8 + tc2;
                if (colb     > row0g)     sa[nb][0] = -1e30f;
                if (colb + 1 > row0g)     sa[nb][1] = -1e30f;
                if (colb     > row0g + 8) sa[nb][2] = -1e30f;
                if (colb + 1 > row0g + 8) sa[nb][3] = -1e30f;
            }
        }

        // ---- O += P V; l += P @ ones. P = ex2.f16x2(pack(S)).
#pragma unroll
        for (int kg = 0; kg < 4; kg++) {
            float* c0 = sa[2 * kg];
            float* c1 = sa[2 * kg + 1];
            uint32_t ap[4];
            ap[0] = h2ex2(pack2h(c0[0], c0[1]));
            ap[1] = h2ex2(pack2h(c0[2], c0[3]));
            ap[2] = h2ex2(pack2h(c1[0], c1[1]));
            ap[3] = h2ex2(pack2h(c1[2], c1[3]));
            mma16816(lacc, ap, bones);
#pragma unroll
            for (int nj = 0; nj < 4; nj++) {
                int rB = rB0 + nj * 16;
                uint32_t offB = (uint32_t)(rB * 128) + (uint32_t)(((kg * 2 + qhB) ^ (rB & 7)) << 4);
                uint32_t bv[4];
                ldmx4(bv, stage + 8192 + offB);
                mma16816(oa[nj*2],   ap, bv);
                mma16816(oa[nj*2+1], ap, bv + 2);
            }
        }
    }

    // lacc columns are identical; [0] = rowsum(row g), [2] = rowsum(row g+8)
    float inv0 = 1.f / lacc[0], inv1 = 1.f / lacc[2];
    uint32_t tb = (uint32_t)(((b * 16 + qt) * 32 + h) * 16384);
    uint32_t* y32 = (uint32_t*)yt;
    const int r0 = warp * 16 + g, r1 = r0 + 8;
#pragma unroll
    for (int nb = 0; nb < 8; nb++) {
        int d0 = nb * 8 + tc2;
        uint32_t off0 = (uint32_t)(r0 * 128 + d0 * 2);
        uint32_t sw0  = off0 ^ ((off0 >> 3) & 0x70);
        y32[(tb + sw0) >> 2] = pack2h(oa[nb][0] * inv0, oa[nb][1] * inv0);
        uint32_t off1 = (uint32_t)(r1 * 128 + d0 * 2);
        uint32_t sw1  = off1 ^ ((off1 >> 3) & 0x70);
        y32[(tb + sw1) >> 2] = pack2h(oa[nb][2] * inv1, oa[nb][3] * inv1);
    }
}

// ---------------------------------------------------------------------------
extern "C" void kernel_launch(void* const* d_in, const int* in_sizes, int n_in,
                              void* d_out, int out_size)
{
    const float* x    = (const float*)d_in[0];
    const float* fcos = (const float*)d_in[1];
    const float* fsin = (const float*)d_in[2];
    const float* wq   = (const float*)d_in[3];
    const float* wk   = (const float*)d_in[4];
    const float* wv   = (const float*)d_in[5];
    const float* wo   = (const float*)d_in[6];
    float* out = (float*)d_out;

    uint4 *xt, *wqt, *wkt, *wvt, *wot;
    __half *qh, *kh, *vh;
    cudaGetSymbolAddress((void**)&xt, g_xt);
    cudaGetSymbolAddress((void**)&wqt, g_wqt);
    cudaGetSymbolAddress((void**)&wkt, g_wkt);
    cudaGetSymbolAddress((void**)&wvt, g_wvt);
    cudaGetSymbolAddress((void**)&wot, g_wot);
    cudaGetSymbolAddress((void**)&qh, g_qh);
    cudaGetSymbolAddress((void**)&kh, g_kh);
    cudaGetSymbolAddress((void**)&vh, g_vh);

    cudaFuncSetAttribute(hgemm, cudaFuncAttributeMaxDynamicSharedMemorySize, HG_SMEM);
    cudaFuncSetAttribute(attn,  cudaFuncAttributeMaxDynamicSharedMemorySize, AT_SMEM);

    dim3 cgrid(512, 6);    // 4 weights + x (2 halves), 4 rows per CTA
    conv_all<<<cgrid, 256>>>(wq, wk, wv, wo, x, wqt, wkt, wvt, wot, xt);

    dim3 ggrid3(Dd / 128, Mrows / 256, 3);   // fused QKV (16,16,3)
    hgemm<<<ggrid3, 256, HG_SMEM>>>(xt, wqt, wkt, wvt, nullptr,
                                    qh, kh, vh, fcos, fsin, 1);

    dim3 agrid(Tt / 128, Hh, Bb);            // (16, 32, 2)
    attn<<<agrid, 256, AT_SMEM>>>(qh, kh, vh, xt);

    dim3 ggrid(Dd / 128, Mrows / 256, 1);    // wo (16,16)
    hgemm<<<ggrid, 256, HG_SMEM>>>(xt, wot, nullptr, nullptr, out,
                                   nullptr, nullptr, nullptr, fcos, fsin, 0);
}

// round 17
// speedup vs baseline: 1.1503x; 1.0550x over previous
#include <cuda_runtime.h>
#include <cuda_fp16.h>
#include <cstdint>
#include <math.h>

#define Bb   2
#define Tt   2048
#define Dd   2048
#define Hh   32
#define HD   64
#define Mrows (Bb*Tt)          // 4096

// ---------------- scratch (__device__ globals) ------------------------------
__device__ uint4 g_xt [(size_t)1024*1024];     // A tiles (plain fp16): x, later y
__device__ uint4 g_wqt[(size_t)512*1024];      // W tiles (plain fp16)
__device__ uint4 g_wkt[(size_t)512*1024];
__device__ uint4 g_wvt[(size_t)512*1024];
__device__ uint4 g_wot[(size_t)512*1024];

// attention planes (plain fp16, PRE-SWIZZLED for direct bulk-copy -> ldmatrix):
// Q,K: [bh][t][d] rows chunk-permuted by (t&7)
// V:   blocked [bh][tc(32)][d(64)][t64] rows chunk-permuted by (d&7)
__device__ __align__(16) __half g_qh[(size_t)64*2048*64];
__device__ __align__(16) __half g_kh[(size_t)64*2048*64];
__device__ __align__(16) __half g_vh[(size_t)64*2048*64];

// ---------------- PTX helpers ----------------------------------------------
__device__ __forceinline__ uint32_t smem_u32(const void* p) {
    return (uint32_t)__cvta_generic_to_shared(p);
}
__device__ __forceinline__ void mbar_init(uint32_t a, uint32_t cnt) {
    asm volatile("mbarrier.init.shared.b64 [%0], %1;" :: "r"(a), "r"(cnt) : "memory");
}
__device__ __forceinline__ void mbar_expect(uint32_t a, uint32_t tx) {
    asm volatile("mbarrier.arrive.expect_tx.shared.b64 _, [%0], %1;" :: "r"(a), "r"(tx) : "memory");
}
__device__ __forceinline__ void mbar_arrive(uint32_t a) {
    asm volatile("mbarrier.arrive.shared.b64 _, [%0];" :: "r"(a) : "memory");
}
__device__ __forceinline__ void mbar_wait(uint32_t a, int parity) {
    asm volatile(
        "{\n\t.reg .pred P;\n\t"
        "WL_%=:\n\t"
        "mbarrier.try_wait.parity.acquire.cta.shared::cta.b64 P, [%0], %1, 0x989680;\n\t"
        "@P bra WD_%=;\n\t"
        "bra WL_%=;\n\t"
        "WD_%=:\n\t}"
        :: "r"(a), "r"(parity) : "memory");
}
__device__ __forceinline__ void bulk_g2s(uint32_t dst, const void* src, uint32_t bytes, uint32_t mbar) {
    asm volatile(
        "cp.async.bulk.shared::cluster.global.mbarrier::complete_tx::bytes [%0], [%1], %2, [%3];"
        :: "r"(dst), "l"(src), "r"(bytes), "r"(mbar) : "memory");
}
__device__ __forceinline__ void ldmx4(uint32_t* r, uint32_t addr) {
    asm volatile("ldmatrix.sync.aligned.m8n8.x4.shared.b16 {%0,%1,%2,%3}, [%4];"
                 : "=r"(r[0]), "=r"(r[1]), "=r"(r[2]), "=r"(r[3]) : "r"(addr));
}
__device__ __forceinline__ void mma16816(float* d, const uint32_t* a, const uint32_t* b) {
    asm volatile(
        "mma.sync.aligned.m16n8k16.row.col.f32.f16.f16.f32 "
        "{%0,%1,%2,%3}, {%4,%5,%6,%7}, {%8,%9}, {%0,%1,%2,%3};"
        : "+f"(d[0]), "+f"(d[1]), "+f"(d[2]), "+f"(d[3])
        : "r"(a[0]), "r"(a[1]), "r"(a[2]), "r"(a[3]), "r"(b[0]), "r"(b[1]));
}
__device__ __forceinline__ uint32_t pack2h(float v0, float v1) {
    __half2 p = __float22half2_rn(make_float2(v0, v1));
    return *(uint32_t*)&p;
}
__device__ __forceinline__ uint32_t h2ex2(uint32_t x) {
    uint32_t y;
    asm("ex2.approx.f16x2 %0, %1;" : "=r"(y) : "r"(x));
    return y;
}

// ---------------------------------------------------------------------------
// Convert fp32 -> plain fp16, tiled 16KB chunks, SW128. One launch covers the
// 4 weights (grid.y 0..3) and x (grid.y 4..5). 4 rows per CTA (MLP=4).
// ---------------------------------------------------------------------------
__global__ __launch_bounds__(256) void conv_all(
    const float* __restrict__ w0, const float* __restrict__ w1,
    const float* __restrict__ w2, const float* __restrict__ w3,
    const float* __restrict__ xs,
    uint4* __restrict__ d0, uint4* __restrict__ d1,
    uint4* __restrict__ d2, uint4* __restrict__ d3,
    uint4* __restrict__ dx)
{
    const int which = blockIdx.y;
    const float* src;
    uint4* dst;
    if (which < 4) {
        src = which == 0 ? w0 : which == 1 ? w1 : which == 2 ? w2 : w3;
        dst = which == 0 ? d0 : which == 1 ? d1 : which == 2 ? d2 : d3;
    } else {
        src = xs + (size_t)(which - 4) * 2048 * Dd;
        dst = dx + (size_t)(which - 4) * 512 * 1024;
    }

    const int c8  = threadIdx.x;
    const int kc  = c8 >> 3;
    const int c16 = c8 & 7;

#pragma unroll
    for (int rr = 0; rr < 4; rr++) {
        int row = blockIdx.x * 4 + rr;
        const int nt = row >> 7, r = row & 127;

        const float4* s = (const float4*)(src + (size_t)row * Dd + c8 * 8);
        float4 f0 = s[0], f1 = s[1];
        float f[8] = {f0.x, f0.y, f0.z, f0.w, f1.x, f1.y, f1.z, f1.w};

        union { __half h[8]; uint4 v; } hv;
#pragma unroll
        for (int i = 0; i < 8; i++) hv.h[i] = __float2half(f[i]);

        uint32_t off = (uint32_t)(r * 128 + c16 * 16);
        uint32_t sw  = off ^ ((off >> 3) & 0x70);
        size_t tb = ((size_t)(nt * 32 + kc)) * 1024;
        dst[tb + sw / 16] = hv.v;
    }
}

// ---------------------------------------------------------------------------
// HMMA GEMM, plain fp16, CTA tile 256x128, warp tile 64x64 (4x2 warps), occ 1.
// 3-stage decoupled producer/consumer pipeline (no per-iter syncthreads).
// fused=1: blockIdx.z -> {Q(mode1), K(mode3), V(mode2)} -- all pre-swizzled.
// fused=0: fp32 C (wo).
// ---------------------------------------------------------------------------
#define HG_STAGE 49152
#define HG_SMEM  (2048 + 3 * HG_STAGE)   // ~146KB

__global__ __launch_bounds__(256, 1) void hgemm(
    const uint4* __restrict__ At,
    const uint4* __restrict__ W0, const uint4* __restrict__ W1,
    const uint4* __restrict__ W2,
    float* __restrict__ C,
    __half* __restrict__ qH, __half* __restrict__ kH, __half* __restrict__ vH,
    const float* __restrict__ fcos, const float* __restrict__ fsin,
    int fused)
{
    extern __shared__ char smraw[];
    const uint32_t base = (smem_u32(smraw) + 1023u) & ~1023u;
    const int tid = threadIdx.x, warp = tid >> 5, lane = tid & 31;
    const int bn = blockIdx.x, bm = blockIdx.y;

    const uint4* Wt; int mode;
    if (fused) {
        int z = blockIdx.z;
        Wt = (z == 0) ? W0 : (z == 1) ? W1 : W2;
        mode = (z == 0) ? 1 : (z == 1) ? 3 : 2;
    } else { Wt = W0; mode = 0; }

    const int wm4 = (warp >> 1) * 64;
    const int wn2 = (warp & 1) * 64;
    const int rA0l = (wm4 & 127) + ((lane >> 3) & 1) * 8 + (lane & 7);
    const uint32_t abase = (uint32_t)((wm4 >> 7) * 16384);
    const int qhA = lane >> 4;
    const int rB0 = wn2 + (lane >> 4) * 8 + (lane & 7);
    const int qhB = (lane >> 3) & 1;

    float acc[4][8][4];
#pragma unroll
    for (int mi = 0; mi < 4; mi++)
#pragma unroll
        for (int nb = 0; nb < 8; nb++)
#pragma unroll
            for (int e = 0; e < 4; e++) acc[mi][nb][e] = 0.f;

    if (tid == 0) {
#pragma unroll
        for (int s = 0; s < 3; s++) { mbar_init(base + s * 8, 1); mbar_init(base + 64 + s * 8, 8); }
    }
    __syncthreads();

    const uint32_t tiles = base + 1024;
    const int mt0 = bm * 2;
    if (tid == 0) {
#pragma unroll
        for (int s = 0; s < 2; s++) {
            mbar_expect(base + s * 8, HG_STAGE);
            uint32_t st = tiles + s * HG_STAGE;
            bulk_g2s(st,         At + (size_t)(mt0 * 32 + s) * 1024,       16384, base + s * 8);
            bulk_g2s(st + 16384, At + (size_t)((mt0 + 1) * 32 + s) * 1024, 16384, base + s * 8);
            bulk_g2s(st + 32768, Wt + (size_t)(bn * 32 + s) * 1024,        16384, base + s * 8);
        }
    }

    int ph[3]  = {0, 0, 0};
    int eph[3] = {0, 0, 0};
    for (int i = 0; i < 32; i++) {
        const int s = i % 3;
        if (tid == 0 && i + 2 < 32) {
            const int s2 = (i + 2) % 3;
            if (i >= 1) { mbar_wait(base + 64 + s2 * 8, eph[s2]); eph[s2] ^= 1; }
            uint32_t full = base + s2 * 8;
            uint32_t st2  = tiles + s2 * HG_STAGE;
            mbar_expect(full, HG_STAGE);
            bulk_g2s(st2,         At + (size_t)(mt0 * 32 + i + 2) * 1024,       16384, full);
            bulk_g2s(st2 + 16384, At + (size_t)((mt0 + 1) * 32 + i + 2) * 1024, 16384, full);
            bulk_g2s(st2 + 32768, Wt + (size_t)(bn * 32 + i + 2) * 1024,        16384, full);
        }
        mbar_wait(base + s * 8, ph[s]); ph[s] ^= 1;

        const uint32_t stg = tiles + s * HG_STAGE;
        const uint32_t sA = stg + abase, sB = stg + 32768;

#pragma unroll
        for (int ks = 0; ks < 4; ks++) {
            uint32_t af[4][4], bf[8][2];
#pragma unroll
            for (int mi = 0; mi < 4; mi++) {
                int row = rA0l + mi * 16;
                uint32_t off = (uint32_t)(row * 128) + (uint32_t)(((ks * 2 + qhA) ^ (row & 7)) << 4);
                ldmx4(af[mi], sA + off);
            }
#pragma unroll
            for (int nj = 0; nj < 4; nj++) {
                int row = rB0 + nj * 16;
                uint32_t off = (uint32_t)(row * 128) + (uint32_t)(((ks * 2 + qhB) ^ (row & 7)) << 4);
                uint32_t t[4];
                ldmx4(t, sB + off);
                bf[nj*2][0] = t[0]; bf[nj*2][1] = t[1];
                bf[nj*2+1][0] = t[2]; bf[nj*2+1][1] = t[3];
            }
#pragma unroll
            for (int mi = 0; mi < 4; mi++)
#pragma unroll
                for (int nb = 0; nb < 8; nb++)
                    mma16816(acc[mi][nb], af[mi], bf[nb]);
        }
        if (lane == 0) mbar_arrive(base + 64 + s * 8);
    }
    __syncthreads();

    // ---- epilogues
    char* smgen = smraw + (int)(tiles - smem_u32(smraw));
    const int bb = (bm * 256) >> 11;
    const int t0 = (bm * 256) & (Tt - 1);

    if (mode == 2) {
        // V: stage transposed fp16, then blocked pre-swizzled [bh][tc][d][64]
        __half* hs = (__half*)smgen;   // stride 264
#pragma unroll
        for (int mi = 0; mi < 4; mi++)
#pragma unroll
            for (int nb = 0; nb < 8; nb++) {
                int jl = wn2 + (lane & 3) * 2 + nb * 8;
#pragma unroll
                for (int half = 0; half < 2; half++) {
                    int ml = wm4 + (lane >> 2) + mi * 16 + half * 8;
                    hs[jl * 264 + ml]       = __float2half(acc[mi][nb][half * 2 + 0]);
                    hs[(jl + 1) * 264 + ml] = __float2half(acc[mi][nb][half * 2 + 1]);
                }
            }
        __syncthreads();
        for (int L = tid; L < 512; L += 256) {
            int j = L >> 2, part = L & 3;
            int d = bn * 128 + j, hh = d >> 6, dd = d & 63;
            int tc = (t0 >> 6) + part;
            __half* dstb = vH + (((size_t)(bb * Hh + hh) * 32 + tc) * 64 + dd) * 64;
            const uint4* srcv = (const uint4*)(hs + j * 264 + part * 64);
#pragma unroll
            for (int u = 0; u < 8; u++)
                *(uint4*)(dstb + ((u ^ (dd & 7)) * 8)) = srcv[u];
        }
        return;
    }

    if (mode == 0) {
        float* sbf = (float*)smgen;   // [128][132]
#pragma unroll
        for (int p = 0; p < 2; p++) {
            if ((warp >> 2) == p) {
#pragma unroll
                for (int mi = 0; mi < 4; mi++)
#pragma unroll
                    for (int nb = 0; nb < 8; nb++) {
                        int jl = wn2 + (lane & 3) * 2 + nb * 8;
#pragma unroll
                        for (int half = 0; half < 2; half++) {
                            int ml = (wm4 & 127) + (lane >> 2) + mi * 16 + half * 8;
                            sbf[ml * 132 + jl]     = acc[mi][nb][half * 2 + 0];
                            sbf[ml * 132 + jl + 1] = acc[mi][nb][half * 2 + 1];
                        }
                    }
            }
            __syncthreads();
#pragma unroll
            for (int r = warp; r < 128; r += 8) {
                float4 v = *(const float4*)&sbf[r * 132 + lane * 4];
                *(float4*)(C + (size_t)(bm * 256 + p * 128 + r) * Dd + bn * 128 + lane * 4) = v;
            }
            __syncthreads();
        }
        return;
    }

    // modes 1 (Q, pre-scaled) and 3 (K): RoPE + staged write, PRE-SWIZZLED rows
    {
        uint32_t* sb = (uint32_t*)smgen;
        const float SCQ = (mode == 1) ? 0.18033688f : 1.0f;  // (1/8)*log2(e)
#pragma unroll
        for (int mi = 0; mi < 4; mi++)
#pragma unroll
            for (int nb = 0; nb < 8; nb++) {
                int jl = wn2 + (lane & 3) * 2 + nb * 8;
                int pi = (jl & 63) >> 1;
#pragma unroll
                for (int half = 0; half < 2; half++) {
                    int ml = wm4 + (lane >> 2) + mi * 16 + half * 8;
                    int t  = (bm * 256 + ml) & (Tt - 1);
                    float cv = fcos[t * (HD / 2) + pi], sv = fsin[t * (HD / 2) + pi];
                    float v0 = acc[mi][nb][half * 2 + 0];
                    float v1 = acc[mi][nb][half * 2 + 1];
                    float r0 = (v0 * cv - v1 * sv) * SCQ;
                    float i0 = (v0 * sv + v1 * cv) * SCQ;
                    sb[ml * 66 + (jl >> 1)] = pack2h(r0, i0);
                }
            }
        __syncthreads();
        int hh0 = bn * 2;
        uint32_t* dstp = (uint32_t*)((mode == 1) ? qH : kH);
        for (int L = warp; L < 512; L += 8) {
            int row = L >> 1;
            int hh  = L & 1;
            uint32_t val = sb[row * 66 + hh * 32 + lane];
            int sl = (((lane >> 2) ^ (row & 7)) << 2) | (lane & 3);
            dstp[((size_t)(bb * Hh + hh0 + hh) * Tt + t0 + row) * 32 + sl] = val;
        }
    }
}

// ---------------------------------------------------------------------------
// Tensor-core flash attention, decoupled mbarrier pipeline (no mainloop sync).
// Planes are pre-swizzled in gmem -> tid0-only cp.async.bulk loads:
//   Q 16KB once; per stage K 8KB + V 8KB (one full barrier, expect 16KB).
// Fixed-shift softmax, l-sums via ones-MMA, exp via ex2.approx.f16x2.
// smem: hdr 1KB | Q 16K | 3 stages x 16K = 66KB (occ 2).
// ---------------------------------------------------------------------------
#define AT_SMEM (1024 + 16384 + 3 * 16384)

__global__ __launch_bounds__(256, 2) void attn(
    const __half* __restrict__ qh,
    const __half* __restrict__ kh, const __half* __restrict__ vh,
    uint4* __restrict__ yt)
{
    extern __shared__ char smraw[];
    const uint32_t base = (smem_u32(smraw) + 1023u) & ~1023u;
    const uint32_t qsm  = base + 1024;
    const uint32_t stg0 = qsm + 16384;
    const int tid = threadIdx.x, warp = tid >> 5, lane = tid & 31;
    const int qt = (int)gridDim.x - 1 - (int)blockIdx.x;
    const int h  = blockIdx.y, b = blockIdx.z;
    const int bh = b * Hh + h;
    const int ktmax = 2 * qt + 2;

    // barriers: qfull @base (cnt1); full[s] @base+8+s*8 (cnt1); empty[s] @base+64+s*8 (cnt8)
    if (tid == 0) {
        mbar_init(base, 1);
#pragma unroll
        for (int s = 0; s < 3; s++) { mbar_init(base + 8 + s * 8, 1); mbar_init(base + 64 + s * 8, 8); }
    }
    __syncthreads();

    if (tid == 0) {
        mbar_expect(base, 16384);
        bulk_g2s(qsm, qh + ((size_t)bh * Tt + qt * 128) * HD, 16384, base);
#pragma unroll
        for (int s = 0; s < 2; s++) {
            mbar_expect(base + 8 + s * 8, 16384);
            bulk_g2s(stg0 + s * 16384,        kh + ((size_t)bh * Tt + s * 64) * HD, 8192, base + 8 + s * 8);
            bulk_g2s(stg0 + s * 16384 + 8192, vh + ((size_t)bh * 32 + s) * 4096,    8192, base + 8 + s * 8);
        }
    }

    const int g    = lane >> 2;
    const int tc2  = (lane & 3) * 2;
    const int rA0  = warp * 16 + ((lane >> 3) & 1) * 8 + (lane & 7);
    const int qhA  = lane >> 4;
    const int rB0  = (lane >> 4) * 8 + (lane & 7);
    const int qhB  = (lane >> 3) & 1;
    const int row0g = qt * 128 + warp * 16 + g;

    // ---- hoist Q fragments (wait Q bulk complete)
    uint32_t qf[4][4];
    mbar_wait(base, 0);
#pragma unroll
    for (int kg = 0; kg < 4; kg++) {
        uint32_t offA = (uint32_t)(rA0 * 128) + (uint32_t)(((kg * 2 + qhA) ^ (rA0 & 7)) << 4);
        ldmx4(qf[kg], qsm + offA);
    }

    float oa[8][4];
#pragma unroll
    for (int nb = 0; nb < 8; nb++)
#pragma unroll
        for (int e = 0; e < 4; e++) oa[nb][e] = 0.f;
    float lacc[4] = {0.f, 0.f, 0.f, 0.f};
    const uint32_t bones[2] = {0x3C003C00u, 0x3C003C00u};

    int ph[3]  = {0, 0, 0};
    int eph[3] = {0, 0, 0};
    for (int kt = 0; kt < ktmax; kt++) {
        const int s = kt % 3;
        if (tid == 0 && kt + 2 < ktmax) {
            const int s2 = (kt + 2) % 3;
            if (kt >= 1) { mbar_wait(base + 64 + s2 * 8, eph[s2]); eph[s2] ^= 1; }
            mbar_expect(base + 8 + s2 * 8, 16384);
            bulk_g2s(stg0 + s2 * 16384,        kh + ((size_t)bh * Tt + (kt + 2) * 64) * HD, 8192, base + 8 + s2 * 8);
            bulk_g2s(stg0 + s2 * 16384 + 8192, vh + ((size_t)bh * 32 + (kt + 2)) * 4096,    8192, base + 8 + s2 * 8);
        }
        mbar_wait(base + 8 + s * 8, ph[s]); ph[s] ^= 1;
        const uint32_t stage = stg0 + (uint32_t)(s * 16384);

        // ---- S = Q K^T (single pass; Q pre-scaled into log2 units)
        float sa[8][4];
#pragma unroll
        for (int nb = 0; nb < 8; nb++)
#pragma unroll
            for (int e = 0; e < 4; e++) sa[nb][e] = 0.f;

#pragma unroll
        for (int kg = 0; kg < 4; kg++) {
#pragma unroll
            for (int nj = 0; nj < 4; nj++) {
                int rB = rB0 + nj * 16;
                uint32_t offB = (uint32_t)(rB * 128) + (uint32_t)(((kg * 2 + qhB) ^ (rB & 7)) << 4);
                uint32_t th[4];
                ldmx4(th, stage + offB);
                mma16816(sa[nj*2],   qf[kg], th);
                mma16816(sa[nj*2+1], qf[kg], th + 2);
            }
        }

        // ---- causal mask
        const bool dm = (kt >= 2 * qt);
        if (dm) {
#pragma unroll
            for (int nb = 0; nb < 8; nb++) {
                int colb = kt * 64 + nb * 8 + tc2;
                if (colb     > row0g)     sa[nb][0] = -1e30f;
                if (colb + 1 > row0g)     sa[nb][1] = -1e30f;
                if (colb     > row0g + 8) sa[nb][2] = -1e30f;
                if (colb + 1 > row0g + 8) sa[nb][3] = -1e30f;
            }
        }

        // ---- O += P V; l += P @ ones. P = ex2.f16x2(pack(S)).
#pragma unroll
        for (int kg = 0; kg < 4; kg++) {
            float* c0 = sa[2 * kg];
            float* c1 = sa[2 * kg + 1];
            uint32_t ap[4];
            ap[0] = h2ex2(pack2h(c0[0], c0[1]));
            ap[1] = h2ex2(pack2h(c0[2], c0[3]));
            ap[2] = h2ex2(pack2h(c1[0], c1[1]));
            ap[3] = h2ex2(pack2h(c1[2], c1[3]));
            mma16816(lacc, ap, bones);
#pragma unroll
            for (int nj = 0; nj < 4; nj++) {
                int rB = rB0 + nj * 16;
                uint32_t offB = (uint32_t)(rB * 128) + (uint32_t)(((kg * 2 + qhB) ^ (rB & 7)) << 4);
                uint32_t bv[4];
                ldmx4(bv, stage + 8192 + offB);
                mma16816(oa[nj*2],   ap, bv);
                mma16816(oa[nj*2+1], ap, bv + 2);
            }
        }
        if (lane == 0) mbar_arrive(base + 64 + s * 8);
    }

    // lacc columns identical; [0] = rowsum(row g), [2] = rowsum(row g+8)
    float inv0 = 1.f / lacc[0], inv1 = 1.f / lacc[2];
    uint32_t tb = (uint32_t)(((b * 16 + qt) * 32 + h) * 16384);
    uint32_t* y32 = (uint32_t*)yt;
    const int r0 = warp * 16 + g, r1 = r0 + 8;
#pragma unroll
    for (int nb = 0; nb < 8; nb++) {
        int d0 = nb * 8 + tc2;
        uint32_t off0 = (uint32_t)(r0 * 128 + d0 * 2);
        uint32_t sw0  = off0 ^ ((off0 >> 3) & 0x70);
        y32[(tb + sw0) >> 2] = pack2h(oa[nb][0] * inv0, oa[nb][1] * inv0);
        uint32_t off1 = (uint32_t)(r1 * 128 + d0 * 2);
        uint32_t sw1  = off1 ^ ((off1 >> 3) & 0x70);
        y32[(tb + sw1) >> 2] = pack2h(oa[nb][2] * inv1, oa[nb][3] * inv1);
    }
}

// ---------------------------------------------------------------------------
extern "C" void kernel_launch(void* const* d_in, const int* in_sizes, int n_in,
                              void* d_out, int out_size)
{
    const float* x    = (const float*)d_in[0];
    const float* fcos = (const float*)d_in[1];
    const float* fsin = (const float*)d_in[2];
    const float* wq   = (const float*)d_in[3];
    const float* wk   = (const float*)d_in[4];
    const float* wv   = (const float*)d_in[5];
    const float* wo   = (const float*)d_in[6];
    float* out = (float*)d_out;

    uint4 *xt, *wqt, *wkt, *wvt, *wot;
    __half *qh, *kh, *vh;
    cudaGetSymbolAddress((void**)&xt, g_xt);
    cudaGetSymbolAddress((void**)&wqt, g_wqt);
    cudaGetSymbolAddress((void**)&wkt, g_wkt);
    cudaGetSymbolAddress((void**)&wvt, g_wvt);
    cudaGetSymbolAddress((void**)&wot, g_wot);
    cudaGetSymbolAddress((void**)&qh, g_qh);
    cudaGetSymbolAddress((void**)&kh, g_kh);
    cudaGetSymbolAddress((void**)&vh, g_vh);

    cudaFuncSetAttribute(hgemm, cudaFuncAttributeMaxDynamicSharedMemorySize, HG_SMEM);
    cudaFuncSetAttribute(attn,  cudaFuncAttributeMaxDynamicSharedMemorySize, AT_SMEM);

    dim3 cgrid(512, 6);    // 4 weights + x (2 halves), 4 rows per CTA
    conv_all<<<cgrid, 256>>>(wq, wk, wv, wo, x, wqt, wkt, wvt, wot, xt);

    dim3 ggrid3(Dd / 128, Mrows / 256, 3);   // fused QKV (16,16,3)
    hgemm<<<ggrid3, 256, HG_SMEM>>>(xt, wqt, wkt, wvt, nullptr,
                                    qh, kh, vh, fcos, fsin, 1);

    dim3 agrid(Tt / 128, Hh, Bb);            // (16, 32, 2)
    attn<<<agrid, 256, AT_SMEM>>>(qh, kh, vh, xt);

    dim3 ggrid(Dd / 128, Mrows / 256, 1);    // wo (16,16)
    hgemm<<<ggrid, 256, HG_SMEM>>>(xt, wot, nullptr, nullptr, out,
                                   nullptr, nullptr, nullptr, fcos, fsin, 0);
}